// round 1
// baseline (speedup 1.0000x reference)
#include <cuda_runtime.h>
#include <math.h>

#define BATCH 4096
#define HID 128
#define NSTEP 16

// ---------------- scratch state (device globals; no allocations) -------------
__device__ float d_h[BATCH * HID];
__device__ float d_c[BATCH * HID];
__device__ float d_x[BATCH * 64];
__device__ float d_gates[BATCH * 512];

// ---------------- init ------------------------------------------------------
__global__ void zero_state_kernel() {
    int i = blockIdx.x * blockDim.x + threadIdx.x;
    if (i < BATCH * HID) { d_h[i] = 0.0f; d_c[i] = 0.0f; }
}

// ---------------- glimpse: gp -> filterbanks -> F_h^T * img * F_w -----------
// one block per batch element, 256 threads
__global__ __launch_bounds__(256) void glimpse_kernel(
    const float* __restrict__ imgs, int sel,
    const float* __restrict__ W_g, const float* __restrict__ b_g)
{
    int b = blockIdx.x;
    int tid = threadIdx.x;

    __shared__ float simg[64 * 64];        // 16 KB
    __shared__ float sF[2][8][64];         // 4 KB  sF[a][t][i] = F_a[i][t]
    __shared__ float stmp[8 * 64];         // 2 KB
    __shared__ float sred[3][8];
    __shared__ float sgp[3];

    const float* img = imgs + ((size_t)b * 2 + (size_t)sel) * 4096;

    // load image tile (coalesced)
#pragma unroll
    for (int j = 0; j < 16; j++)
        simg[tid + j * 256] = img[tid + j * 256];

    // gp = tanh(h @ W_g^T + b_g)
    float v = 0.0f;
    if (tid < HID) v = d_h[b * HID + tid];
#pragma unroll
    for (int k = 0; k < 3; k++) {
        float p = (tid < HID) ? v * W_g[k * HID + tid] : 0.0f;
#pragma unroll
        for (int o = 16; o > 0; o >>= 1) p += __shfl_down_sync(0xffffffffu, p, o);
        if ((tid & 31) == 0) sred[k][tid >> 5] = p;
    }
    __syncthreads();
    if (tid < 3) {
        float s = 0.0f;
#pragma unroll
        for (int w = 0; w < 8; w++) s += sred[tid][w];
        sgp[tid] = tanhf(s + b_g[tid]);
    }
    __syncthreads();

    float delta = sgp[2];
    float ad    = fabsf(delta);
    float dlt   = 8.0f * (1.0f - ad);            // fl/tl * (1-|d|) = 64/8 * ..
    float gam   = expf(1.0f - 2.0f * ad);
    float inv_gam = 1.0f / gam;
    float cpre  = 1.0f / (3.14159265358979323f * gam);

    // unnormalized Cauchy filters: 2 banks * 8 * 64 = 1024 entries
#pragma unroll
    for (int j = 0; j < 4; j++) {
        int idx = tid + j * 256;
        int a = idx >> 9;
        int t = (idx >> 6) & 7;
        int i = idx & 63;
        float center = 31.5f * (sgp[a] + 1.0f);
        float gpix = center + dlt * ((float)t - 3.5f);
        float u = ((float)i - gpix) * inv_gam;
        sF[a][t][i] = cpre / (1.0f + u * u);
    }
    __syncthreads();

    // normalize each (a,t) column over i: 16 columns, 8 warps -> 2 each
    {
        int warp = tid >> 5, lane = tid & 31;
#pragma unroll
        for (int j = 0; j < 2; j++) {
            int col = warp * 2 + j;
            int a = col >> 3, t = col & 7;
            float s = sF[a][t][lane] + sF[a][t][lane + 32];
#pragma unroll
            for (int o = 16; o > 0; o >>= 1) s += __shfl_down_sync(0xffffffffu, s, o);
            s = __shfl_sync(0xffffffffu, s, 0);
            float inv = 1.0f / (s + 1e-4f);
            sF[a][t][lane]      *= inv;
            sF[a][t][lane + 32] *= inv;
        }
    }
    __syncthreads();

    // tmp[t][w] = sum_i F_h[i][t] * img[i][w]
#pragma unroll
    for (int j = 0; j < 2; j++) {
        int idx = tid + j * 256;       // 0..511
        int t = idx >> 6, w = idx & 63;
        float acc = 0.0f;
#pragma unroll 8
        for (int i = 0; i < 64; i++)
            acc = fmaf(sF[0][t][i], simg[i * 64 + w], acc);
        stmp[idx] = acc;
    }
    __syncthreads();

    // x[t*8+s] = sum_w tmp[t][w] * F_w[w][s]
    if (tid < 64) {
        int t = tid >> 3, s = tid & 7;
        float acc = 0.0f;
#pragma unroll 8
        for (int w = 0; w < 64; w++)
            acc = fmaf(stmp[t * 64 + w], sF[1][s][w], acc);
        d_x[b * 64 + tid] = acc;
    }
}

// ---------------- gates GEMM: [4096,192] @ [192,512] + biases ----------------
// BM=64, BN=128, BK=32, 256 threads, thread tile 8x4 (cols strided by 32)
__global__ __launch_bounds__(256) void gemm_kernel(
    const float* __restrict__ W_ih, const float* __restrict__ W_hh,
    const float* __restrict__ b_ih, const float* __restrict__ b_hh)
{
    __shared__ float sA[64 * 32];        // 8 KB   sA[r][k]
    __shared__ float sBt[128 * 33];      // 16.5KB sBt[n][k] (padded)

    int tid = threadIdx.x;
    int cg = tid & 31;        // lane -> column group
    int rg = tid >> 5;        // warp -> row group
    int bm0 = blockIdx.x * 64;
    int bn0 = blockIdx.y * 128;

    float acc[8][4];
#pragma unroll
    for (int r = 0; r < 8; r++)
#pragma unroll
        for (int c = 0; c < 4; c++) acc[r][c] = 0.0f;

    for (int ck = 0; ck < 6; ck++) {
        int kk0 = ck * 32;
        int k_l = cg;
        int kg = kk0 + k_l;
        // load A tile: 64x32 (k-fast coalesced)
#pragma unroll
        for (int j = 0; j < 8; j++) {
            int r = rg + j * 8;
            int row = bm0 + r;
            float va;
            if (kg < 64) va = d_x[row * 64 + kg];
            else         va = d_h[row * 128 + (kg - 64)];
            sA[r * 32 + k_l] = va;
        }
        // load B tile transposed: sBt[n][k], conflict-free STS
#pragma unroll
        for (int j = 0; j < 16; j++) {
            int n_l = rg + j * 8;
            int ng = bn0 + n_l;
            float wv;
            if (kg < 64) wv = W_ih[ng * 64 + kg];
            else         wv = W_hh[ng * 128 + (kg - 64)];
            sBt[n_l * 33 + k_l] = wv;
        }
        __syncthreads();

#pragma unroll 8
        for (int kk = 0; kk < 32; kk++) {
            float ar[8], bc[4];
#pragma unroll
            for (int rr = 0; rr < 8; rr++) ar[rr] = sA[(rg * 8 + rr) * 32 + kk];
#pragma unroll
            for (int c = 0; c < 4; c++)   bc[c] = sBt[(cg + 32 * c) * 33 + kk];
#pragma unroll
            for (int rr = 0; rr < 8; rr++)
#pragma unroll
                for (int c = 0; c < 4; c++)
                    acc[rr][c] = fmaf(ar[rr], bc[c], acc[rr][c]);
        }
        __syncthreads();
    }

    // epilogue: add biases, write gates
    float bias[4];
#pragma unroll
    for (int c = 0; c < 4; c++) {
        int n = bn0 + cg + 32 * c;
        bias[c] = __ldg(&b_ih[n]) + __ldg(&b_hh[n]);
    }
#pragma unroll
    for (int rr = 0; rr < 8; rr++) {
        int row = bm0 + rg * 8 + rr;
#pragma unroll
        for (int c = 0; c < 4; c++) {
            int n = bn0 + cg + 32 * c;
            d_gates[row * 512 + n] = acc[rr][c] + bias[c];
        }
    }
}

// ---------------- LSTM pointwise --------------------------------------------
__device__ __forceinline__ float sigf(float x) { return 1.0f / (1.0f + expf(-x)); }

__global__ __launch_bounds__(256) void lstm_kernel(float* __restrict__ out, int last)
{
    int idx = blockIdx.x * blockDim.x + threadIdx.x;
    if (idx >= BATCH * HID) return;
    int b = idx >> 7, j = idx & 127;
    const float* gr = d_gates + b * 512;
    float gi = gr[j];
    float gf = gr[128 + j];
    float gg = gr[256 + j];
    float go = gr[384 + j];
    float cv = d_c[idx];
    float cn = sigf(gf) * cv + sigf(gi) * tanhf(gg);
    float hn = sigf(go) * tanhf(cn);
    d_c[idx] = cn;
    if (last) out[idx] = hn;
    else      d_h[idx] = hn;
}

// ---------------- launch ----------------------------------------------------
extern "C" void kernel_launch(void* const* d_in, const int* in_sizes, int n_in,
                              void* d_out, int out_size)
{
    const float* imgs = (const float*)d_in[0];   // [4096, 2, 64, 64]
    const float* W_ih = (const float*)d_in[1];   // [512, 64]
    const float* W_hh = (const float*)d_in[2];   // [512, 128]
    const float* b_ih = (const float*)d_in[3];   // [512]
    const float* b_hh = (const float*)d_in[4];   // [512]
    const float* W_g  = (const float*)d_in[5];   // [3, 128]
    const float* b_g  = (const float*)d_in[6];   // [3]
    float* out = (float*)d_out;                  // [4096, 128]

    zero_state_kernel<<<(BATCH * HID + 255) / 256, 256>>>();

    for (int t = 0; t < NSTEP; t++) {
        glimpse_kernel<<<BATCH, 256>>>(imgs, t & 1, W_g, b_g);
        gemm_kernel<<<dim3(BATCH / 64, 4), 256>>>(W_ih, W_hh, b_ih, b_hh);
        lstm_kernel<<<(BATCH * HID + 255) / 256, 256>>>(out, t == NSTEP - 1 ? 1 : 0);
    }
}

// round 3
// speedup vs baseline: 1.2269x; 1.2269x over previous
#include <cuda_runtime.h>
#include <cuda_bf16.h>
#include <math.h>
#include <stdint.h>

#define BATCH 4096
#define HID 128
#define NSTEP 16

// ---------------- persistent state (device globals; no allocations) ----------
__device__ float d_h[BATCH * HID];
__device__ float d_c[BATCH * HID];
__device__ __align__(16) __nv_bfloat16 d_h_hi[BATCH * HID];
__device__ __align__(16) __nv_bfloat16 d_h_lo[BATCH * HID];
__device__ __align__(16) __nv_bfloat16 d_x_hi[BATCH * 64];
__device__ __align__(16) __nv_bfloat16 d_x_lo[BATCH * 64];
__device__ __align__(16) __nv_bfloat16 d_W_hi[512 * 192];   // reordered cols: n' = j*4+gate
__device__ __align__(16) __nv_bfloat16 d_W_lo[512 * 192];
__device__ __align__(16) float d_bias[512];                  // reordered

// ---------------- helpers ----------------------------------------------------
__device__ __forceinline__ uint32_t smem_u32(const void* p) {
    uint32_t a;
    asm("{ .reg .u64 t; cvta.to.shared.u64 t, %1; cvt.u32.u64 %0, t; }" : "=r"(a) : "l"(p));
    return a;
}
__device__ __forceinline__ void cp_async16(uint32_t dst, const void* src) {
    asm volatile("cp.async.cg.shared.global [%0], [%1], 16;" :: "r"(dst), "l"(src) : "memory");
}
__device__ __forceinline__ void cp_commit() {
    asm volatile("cp.async.commit_group;" ::: "memory");
}
template <int N>
__device__ __forceinline__ void cp_wait() {
    asm volatile("cp.async.wait_group %0;" :: "n"(N) : "memory");
}
__device__ __forceinline__ uint32_t lds32(uint32_t a) {
    uint32_t v;
    asm volatile("ld.shared.b32 %0, [%1];" : "=r"(v) : "r"(a));
    return v;
}
__device__ __forceinline__ void mma_bf16(float* d, const uint32_t* a, const uint32_t* b) {
    asm volatile(
        "mma.sync.aligned.m16n8k16.row.col.f32.bf16.bf16.f32 "
        "{%0,%1,%2,%3}, {%4,%5,%6,%7}, {%8,%9}, {%0,%1,%2,%3};"
        : "+f"(d[0]), "+f"(d[1]), "+f"(d[2]), "+f"(d[3])
        : "r"(a[0]), "r"(a[1]), "r"(a[2]), "r"(a[3]), "r"(b[0]), "r"(b[1]));
}

// ---------------- prologue kernels -------------------------------------------
__global__ void zero_state_kernel() {
    int i = blockIdx.x * blockDim.x + threadIdx.x;
    if (i < BATCH * HID) {
        d_h[i] = 0.0f; d_c[i] = 0.0f;
        d_h_hi[i] = __float2bfloat16(0.0f);
        d_h_lo[i] = __float2bfloat16(0.0f);
    }
}

// reorder columns: n' = j*4 + gate (gate: 0=i,1=f,2=g,3=o), split fp32->bf16 hi/lo
__global__ void prep_weights_kernel(const float* __restrict__ W_ih,
                                    const float* __restrict__ W_hh,
                                    const float* __restrict__ b_ih,
                                    const float* __restrict__ b_hh) {
    int idx = blockIdx.x * blockDim.x + threadIdx.x;   // 512*192
    if (idx >= 512 * 192) return;
    int np = idx / 192, k = idx % 192;
    int gate = np & 3, j = np >> 2;
    int orig = gate * 128 + j;
    float w = (k < 64) ? W_ih[orig * 64 + k] : W_hh[orig * 128 + (k - 64)];
    __nv_bfloat16 hi = __float2bfloat16(w);
    __nv_bfloat16 lo = __float2bfloat16(w - __bfloat162float(hi));
    d_W_hi[np * 192 + k] = hi;
    d_W_lo[np * 192 + k] = lo;
    if (k == 0) d_bias[np] = b_ih[orig] + b_hh[orig];
}

// ---------------- glimpse ----------------------------------------------------
__global__ __launch_bounds__(256) void glimpse_kernel(
    const float* __restrict__ imgs, int sel,
    const float* __restrict__ W_g, const float* __restrict__ b_g)
{
    int b = blockIdx.x;
    int tid = threadIdx.x;

    __shared__ float simg[64 * 64];
    __shared__ float sF[2][8][64];
    __shared__ float stmp[8 * 64];
    __shared__ float sred[3][8];
    __shared__ float sgp[3];

    const float4* img4 = reinterpret_cast<const float4*>(
        imgs + ((size_t)b * 2 + (size_t)sel) * 4096);
    float4* s4 = reinterpret_cast<float4*>(simg);
#pragma unroll
    for (int j = 0; j < 4; j++)
        s4[tid + j * 256] = img4[tid + j * 256];

    float v = 0.0f;
    if (tid < HID) v = d_h[b * HID + tid];
#pragma unroll
    for (int k = 0; k < 3; k++) {
        float p = (tid < HID) ? v * W_g[k * HID + tid] : 0.0f;
#pragma unroll
        for (int o = 16; o > 0; o >>= 1) p += __shfl_down_sync(0xffffffffu, p, o);
        if ((tid & 31) == 0) sred[k][tid >> 5] = p;
    }
    __syncthreads();
    if (tid < 3) {
        float s = 0.0f;
#pragma unroll
        for (int w = 0; w < 8; w++) s += sred[tid][w];
        sgp[tid] = tanhf(s + b_g[tid]);
    }
    __syncthreads();

    float ad  = fabsf(sgp[2]);
    float dlt = 8.0f * (1.0f - ad);
    float gam = expf(1.0f - 2.0f * ad);
    float inv_gam = 1.0f / gam;
    float cpre = 1.0f / (3.14159265358979323f * gam);

#pragma unroll
    for (int j = 0; j < 4; j++) {
        int idx = tid + j * 256;
        int a = idx >> 9, t = (idx >> 6) & 7, i = idx & 63;
        float center = 31.5f * (sgp[a] + 1.0f);
        float gpix = center + dlt * ((float)t - 3.5f);
        float u = ((float)i - gpix) * inv_gam;
        sF[a][t][i] = cpre / (1.0f + u * u);
    }
    __syncthreads();

    {
        int warp = tid >> 5, lane = tid & 31;
#pragma unroll
        for (int j = 0; j < 2; j++) {
            int col = warp * 2 + j;
            int a = col >> 3, t = col & 7;
            float s = sF[a][t][lane] + sF[a][t][lane + 32];
#pragma unroll
            for (int o = 16; o > 0; o >>= 1) s += __shfl_down_sync(0xffffffffu, s, o);
            s = __shfl_sync(0xffffffffu, s, 0);
            float inv = 1.0f / (s + 1e-4f);
            sF[a][t][lane]      *= inv;
            sF[a][t][lane + 32] *= inv;
        }
    }
    __syncthreads();

#pragma unroll
    for (int j = 0; j < 2; j++) {
        int idx = tid + j * 256;
        int t = idx >> 6, w = idx & 63;
        float acc = 0.0f;
#pragma unroll 8
        for (int i = 0; i < 64; i++)
            acc = fmaf(sF[0][t][i], simg[i * 64 + w], acc);
        stmp[idx] = acc;
    }
    __syncthreads();

    if (tid < 64) {
        int t = tid >> 3, s = tid & 7;
        float acc = 0.0f;
#pragma unroll 8
        for (int w = 0; w < 64; w++)
            acc = fmaf(stmp[t * 64 + w], sF[1][s][w], acc);
        __nv_bfloat16 hi = __float2bfloat16(acc);
        __nv_bfloat16 lo = __float2bfloat16(acc - __bfloat162float(hi));
        d_x_hi[b * 64 + tid] = hi;
        d_x_lo[b * 64 + tid] = lo;
    }
}

// ---------------- fused GEMM (mma.sync bf16 split) + LSTM --------------------
// grid (32, 4), 256 threads = 8 warps (4 x 2). CTA tile M=128 x N=128.
// Effective K = 9 chunks of 64 (3 split terms x 3 k-blocks), double-buffered.
// smem:
//   sA[2]: 128 rows x 144B (64 bf16 + 8 pad)   2 x 18432
//   sB[2]: same                                 2 x 18432
//   g_s:   128 x 136 floats                     69632
#define SA_OFF(b) ((b) * 18432)
#define SB_OFF(b) (36864 + (b) * 18432)
#define SG_OFF    73728
#define GS_TOTAL  (73728 + 69632)

__global__ __launch_bounds__(256) void gemm_lstm_kernel(float* __restrict__ out, int last)
{
    extern __shared__ char smem[];
    uint32_t sb = smem_u32(smem);
    int tid = threadIdx.x;
    int wid = tid >> 5, lane = tid & 31;
    int wm = wid & 3, wn = wid >> 2;          // warp tile: rows wm*32..+31, cols wn*64..+63
    int bm0 = blockIdx.x * 128;
    int bn0 = blockIdx.y * 128;
    int j0 = bn0 >> 2;

    // split terms: (a_split, b_split)
    const int tva[3] = {0, 0, 1};
    const int tvb[3] = {0, 1, 0};

    float acc[2][8][4];
#pragma unroll
    for (int mt = 0; mt < 2; mt++)
#pragma unroll
        for (int nt = 0; nt < 8; nt++)
#pragma unroll
            for (int q = 0; q < 4; q++) acc[mt][nt][q] = 0.0f;

    int ldr = tid >> 3;          // 0..31 rows per pass (x4 passes)
    int ldc = tid & 7;           // 16B segment

    // chunk load: c in 0..8 -> term c/3, kblock c%3
#define ISSUE_LOADS(c, buf) do {                                                   \
        int t_ = (c) / 3, kb_ = (c) % 3;                                           \
        const __nv_bfloat16* xs_ = tva[t_] ? d_x_lo : d_x_hi;                      \
        const __nv_bfloat16* hs_ = tva[t_] ? d_h_lo : d_h_hi;                      \
        const __nv_bfloat16* ws_ = tvb[t_] ? d_W_lo : d_W_hi;                      \
        _Pragma("unroll")                                                          \
        for (int p_ = 0; p_ < 4; p_++) {                                           \
            int r_ = ldr + p_ * 32;                                                \
            const __nv_bfloat16* ga_;                                              \
            if (kb_ == 0) ga_ = xs_ + (bm0 + r_) * 64 + ldc * 8;                   \
            else          ga_ = hs_ + (bm0 + r_) * 128 + (kb_ - 1) * 64 + ldc * 8; \
            cp_async16(sb + SA_OFF(buf) + r_ * 144 + ldc * 16, ga_);               \
            const __nv_bfloat16* gb_ = ws_ + (bn0 + r_) * 192 + kb_ * 64 + ldc * 8;\
            cp_async16(sb + SB_OFF(buf) + r_ * 144 + ldc * 16, gb_);               \
        }                                                                          \
        cp_commit();                                                               \
    } while (0)

    ISSUE_LOADS(0, 0);

    for (int c = 0; c < 9; c++) {
        int buf = c & 1;
        if (c < 8) ISSUE_LOADS(c + 1, buf ^ 1);
        if (c < 8) cp_wait<1>(); else cp_wait<0>();
        __syncthreads();

        uint32_t abase = sb + SA_OFF(buf) + (wm * 32 + (lane >> 2)) * 144 + (lane & 3) * 4;
        uint32_t bbase = sb + SB_OFF(buf) + (wn * 64 + (lane >> 2)) * 144 + (lane & 3) * 4;

#pragma unroll
        for (int ks = 0; ks < 4; ks++) {
            uint32_t a[2][4], bfr[8][2];
#pragma unroll
            for (int mt = 0; mt < 2; mt++) {
                uint32_t ab = abase + mt * (16 * 144) + ks * 32;
                a[mt][0] = lds32(ab);
                a[mt][1] = lds32(ab + 8 * 144);
                a[mt][2] = lds32(ab + 16);
                a[mt][3] = lds32(ab + 8 * 144 + 16);
            }
#pragma unroll
            for (int nt = 0; nt < 8; nt++) {
                uint32_t bbp = bbase + nt * (8 * 144) + ks * 32;
                bfr[nt][0] = lds32(bbp);
                bfr[nt][1] = lds32(bbp + 16);
            }
#pragma unroll
            for (int mt = 0; mt < 2; mt++)
#pragma unroll
                for (int nt = 0; nt < 8; nt++)
                    mma_bf16(acc[mt][nt], a[mt], bfr[nt]);
        }
        __syncthreads();
    }
#undef ISSUE_LOADS

    // store accumulators to gates smem tile
    float* g_s = reinterpret_cast<float*>(smem + SG_OFF);   // [128][136]
    {
        int r0 = wm * 32 + (lane >> 2);
        int c0 = wn * 64 + (lane & 3) * 2;
#pragma unroll
        for (int mt = 0; mt < 2; mt++)
#pragma unroll
            for (int nt = 0; nt < 8; nt++) {
                int row = r0 + mt * 16;
                int col = c0 + nt * 8;
                *reinterpret_cast<float2*>(&g_s[row * 136 + col]) =
                    make_float2(acc[mt][nt][0], acc[mt][nt][1]);
                *reinterpret_cast<float2*>(&g_s[(row + 8) * 136 + col]) =
                    make_float2(acc[mt][nt][2], acc[mt][nt][3]);
            }
    }
    __syncthreads();

    // LSTM pointwise, coalesced global traffic
    const float4* bias4 = reinterpret_cast<const float4*>(d_bias + bn0);
    for (int i = tid; i < 128 * 32; i += 256) {
        int row = i >> 5, j = i & 31;
        float4 g4 = *reinterpret_cast<const float4*>(&g_s[row * 136 + 4 * j]);
        float4 b4 = __ldg(&bias4[j]);
        float gi = g4.x + b4.x;
        float gf = g4.y + b4.y;
        float gg = g4.z + b4.z;
        float go = g4.w + b4.w;
        int gidx = (bm0 + row) * 128 + j0 + j;
        float co = d_c[gidx];
        float si = 1.0f / (1.0f + expf(-gi));
        float sf = 1.0f / (1.0f + expf(-gf));
        float so = 1.0f / (1.0f + expf(-go));
        float cn = sf * co + si * tanhf(gg);
        float hn = so * tanhf(cn);
        d_c[gidx] = cn;
        if (last) {
            out[gidx] = hn;
        } else {
            d_h[gidx] = hn;
            __nv_bfloat16 hi = __float2bfloat16(hn);
            d_h_hi[gidx] = hi;
            d_h_lo[gidx] = __float2bfloat16(hn - __bfloat162float(hi));
        }
    }
}

// ---------------- launch ----------------------------------------------------
extern "C" void kernel_launch(void* const* d_in, const int* in_sizes, int n_in,
                              void* d_out, int out_size)
{
    const float* imgs = (const float*)d_in[0];
    const float* W_ih = (const float*)d_in[1];
    const float* W_hh = (const float*)d_in[2];
    const float* b_ih = (const float*)d_in[3];
    const float* b_hh = (const float*)d_in[4];
    const float* W_g  = (const float*)d_in[5];
    const float* b_g  = (const float*)d_in[6];
    float* out = (float*)d_out;

    static int smem_set = 0;
    if (!smem_set) {
        cudaFuncSetAttribute(gemm_lstm_kernel,
                             cudaFuncAttributeMaxDynamicSharedMemorySize, GS_TOTAL);
        smem_set = 1;
    }

    zero_state_kernel<<<(BATCH * HID + 255) / 256, 256>>>();
    prep_weights_kernel<<<(512 * 192 + 255) / 256, 256>>>(W_ih, W_hh, b_ih, b_hh);

    for (int t = 0; t < NSTEP; t++) {
        glimpse_kernel<<<BATCH, 256>>>(imgs, t & 1, W_g, b_g);
        gemm_lstm_kernel<<<dim3(32, 4), 256, GS_TOTAL>>>(out, t == NSTEP - 1 ? 1 : 0);
    }
}

// round 4
// speedup vs baseline: 1.6859x; 1.3741x over previous
#include <cuda_runtime.h>
#include <cuda_bf16.h>
#include <math.h>
#include <stdint.h>

#define BATCH 4096
#define HID 128
#define NSTEP 16

// ---------------- persistent state (device globals; no allocations) ----------
__device__ float d_h[BATCH * HID];
__device__ float d_c[BATCH * HID];
__device__ __align__(16) __nv_bfloat16 d_h_hi[BATCH * HID];
__device__ __align__(16) __nv_bfloat16 d_h_lo[BATCH * HID];
__device__ __align__(16) __nv_bfloat16 d_x_hi[BATCH * 64];
__device__ __align__(16) __nv_bfloat16 d_x_lo[BATCH * 64];
__device__ __align__(16) __nv_bfloat16 d_W_hi[512 * 192];   // reordered cols: n' = j*4+gate
__device__ __align__(16) __nv_bfloat16 d_W_lo[512 * 192];
__device__ __align__(16) float d_bias[512];                  // reordered

// ---------------- helpers ----------------------------------------------------
__device__ __forceinline__ uint32_t smem_u32(const void* p) {
    uint32_t a;
    asm("{ .reg .u64 t; cvta.to.shared.u64 t, %1; cvt.u32.u64 %0, t; }" : "=r"(a) : "l"(p));
    return a;
}
__device__ __forceinline__ void cp_async16(uint32_t dst, const void* src) {
    asm volatile("cp.async.cg.shared.global [%0], [%1], 16;" :: "r"(dst), "l"(src) : "memory");
}
__device__ __forceinline__ void cp_commit() {
    asm volatile("cp.async.commit_group;" ::: "memory");
}
template <int N>
__device__ __forceinline__ void cp_wait() {
    asm volatile("cp.async.wait_group %0;" :: "n"(N) : "memory");
}
__device__ __forceinline__ void ldm_x4(uint32_t* r, uint32_t a) {
    asm volatile("ldmatrix.sync.aligned.m8n8.x4.shared.b16 {%0,%1,%2,%3}, [%4];"
                 : "=r"(r[0]), "=r"(r[1]), "=r"(r[2]), "=r"(r[3]) : "r"(a));
}
__device__ __forceinline__ void ldm_x2(uint32_t* r, uint32_t a) {
    asm volatile("ldmatrix.sync.aligned.m8n8.x2.shared.b16 {%0,%1}, [%2];"
                 : "=r"(r[0]), "=r"(r[1]) : "r"(a));
}
__device__ __forceinline__ void mma_bf16(float* d, const uint32_t* a, const uint32_t* b) {
    asm volatile(
        "mma.sync.aligned.m16n8k16.row.col.f32.bf16.bf16.f32 "
        "{%0,%1,%2,%3}, {%4,%5,%6,%7}, {%8,%9}, {%0,%1,%2,%3};"
        : "+f"(d[0]), "+f"(d[1]), "+f"(d[2]), "+f"(d[3])
        : "r"(a[0]), "r"(a[1]), "r"(a[2]), "r"(a[3]), "r"(b[0]), "r"(b[1]));
}

// ---------------- prologue kernels -------------------------------------------
__global__ void zero_state_kernel() {
    int i = blockIdx.x * blockDim.x + threadIdx.x;
    if (i < BATCH * HID) {
        d_h[i] = 0.0f; d_c[i] = 0.0f;
        d_h_hi[i] = __float2bfloat16(0.0f);
        d_h_lo[i] = __float2bfloat16(0.0f);
    }
}

// reorder columns: n' = j*4 + gate (gate: 0=i,1=f,2=g,3=o), split fp32->bf16 hi/lo
__global__ void prep_weights_kernel(const float* __restrict__ W_ih,
                                    const float* __restrict__ W_hh,
                                    const float* __restrict__ b_ih,
                                    const float* __restrict__ b_hh) {
    int idx = blockIdx.x * blockDim.x + threadIdx.x;   // 512*192
    if (idx >= 512 * 192) return;
    int np = idx / 192, k = idx % 192;
    int gate = np & 3, j = np >> 2;
    int orig = gate * 128 + j;
    float w = (k < 64) ? W_ih[orig * 64 + k] : W_hh[orig * 128 + (k - 64)];
    __nv_bfloat16 hi = __float2bfloat16(w);
    __nv_bfloat16 lo = __float2bfloat16(w - __bfloat162float(hi));
    d_W_hi[np * 192 + k] = hi;
    d_W_lo[np * 192 + k] = lo;
    if (k == 0) d_bias[np] = b_ih[orig] + b_hh[orig];
}

// ---------------- glimpse ----------------------------------------------------
// dynamic smem layout (bytes):
//   simg   @0      16384   [64][64]
//   sF     @16384   4096   [2][8][64]   sF[a][t][i] = F_a[i][t]
//   sFwT   @20480   2048   [64][8]      F_w[w][s]
//   part   @22528  32768   [16][8][64]
//   tmp    @55296   2176   [8][68]
//   xpart  @57472   1024   [4][64]
//   sred   @58496     96   [3][8]
//   sgp    @58592     12
#define GL_TOTAL 58624

__global__ __launch_bounds__(256) void glimpse_kernel(
    const float* __restrict__ imgs, int sel,
    const float* __restrict__ W_g, const float* __restrict__ b_g)
{
    extern __shared__ char gsm[];
    float* simg  = reinterpret_cast<float*>(gsm);
    float* sF    = reinterpret_cast<float*>(gsm + 16384);
    float* sFwT  = reinterpret_cast<float*>(gsm + 20480);
    float* part  = reinterpret_cast<float*>(gsm + 22528);
    float* tmp   = reinterpret_cast<float*>(gsm + 55296);
    float* xpart = reinterpret_cast<float*>(gsm + 57472);
    float* sred  = reinterpret_cast<float*>(gsm + 58496);
    float* sgp   = reinterpret_cast<float*>(gsm + 58592);

    int b = blockIdx.x;
    int tid = threadIdx.x;

    const float4* img4 = reinterpret_cast<const float4*>(
        imgs + ((size_t)b * 2 + (size_t)sel) * 4096);
    float4* s4 = reinterpret_cast<float4*>(simg);
#pragma unroll
    for (int j = 0; j < 4; j++)
        s4[tid + j * 256] = img4[tid + j * 256];

    // gp = tanh(h @ W_g^T + b_g)
    float v = 0.0f;
    if (tid < HID) v = d_h[b * HID + tid];
#pragma unroll
    for (int k = 0; k < 3; k++) {
        float p = (tid < HID) ? v * W_g[k * HID + tid] : 0.0f;
#pragma unroll
        for (int o = 16; o > 0; o >>= 1) p += __shfl_down_sync(0xffffffffu, p, o);
        if ((tid & 31) == 0) sred[k * 8 + (tid >> 5)] = p;
    }
    __syncthreads();
    if (tid < 3) {
        float s = 0.0f;
#pragma unroll
        for (int w = 0; w < 8; w++) s += sred[tid * 8 + w];
        sgp[tid] = tanhf(s + b_g[tid]);
    }
    __syncthreads();

    float ad  = fabsf(sgp[2]);
    float dlt = 8.0f * (1.0f - ad);
    float gam = expf(1.0f - 2.0f * ad);
    float inv_gam = 1.0f / gam;
    float cpre = 1.0f / (3.14159265358979323f * gam);

    // unnormalized Cauchy filters
#pragma unroll
    for (int j = 0; j < 4; j++) {
        int idx = tid + j * 256;
        int a = idx >> 9, t = (idx >> 6) & 7, i = idx & 63;
        float center = 31.5f * (sgp[a] + 1.0f);
        float gpix = center + dlt * ((float)t - 3.5f);
        float u = ((float)i - gpix) * inv_gam;
        sF[(a * 8 + t) * 64 + i] = cpre / (1.0f + u * u);
    }
    __syncthreads();

    // normalize 16 (a,t) columns over i
    {
        int warp = tid >> 5, lane = tid & 31;
#pragma unroll
        for (int j = 0; j < 2; j++) {
            int col = warp * 2 + j;               // 0..15 -> a = col>>3, t = col&7
            float* fc = sF + col * 64;
            float s = fc[lane] + fc[lane + 32];
#pragma unroll
            for (int o = 16; o > 0; o >>= 1) s += __shfl_down_sync(0xffffffffu, s, o);
            s = __shfl_sync(0xffffffffu, s, 0);
            float inv = 1.0f / (s + 1e-4f);
            fc[lane]      *= inv;
            fc[lane + 32] *= inv;
        }
    }
    __syncthreads();

    // transposed F_w copy: sFwT[w][s] = sF[1][s][w]
#pragma unroll
    for (int j = 0; j < 2; j++) {
        int idx = tid + j * 256;
        int w = idx >> 3, s = idx & 7;
        sFwT[w * 8 + s] = sF[(8 + s) * 64 + w];
    }
    __syncthreads();

    // phase B: part[q][t][w] — thread = (wg 0..15 [4 w], q 0..15 [4 i])
    {
        int wg = tid & 15, q = tid >> 4;
        float acc[8][4];
#pragma unroll
        for (int t = 0; t < 8; t++)
#pragma unroll
            for (int u = 0; u < 4; u++) acc[t][u] = 0.0f;
        const float4* sg4 = reinterpret_cast<const float4*>(simg);
#pragma unroll
        for (int ii = 0; ii < 4; ii++) {
            int i = q * 4 + ii;
            float4 im = sg4[i * 16 + wg];
#pragma unroll
            for (int t = 0; t < 8; t++) {
                float f = sF[t * 64 + i];
                acc[t][0] = fmaf(f, im.x, acc[t][0]);
                acc[t][1] = fmaf(f, im.y, acc[t][1]);
                acc[t][2] = fmaf(f, im.z, acc[t][2]);
                acc[t][3] = fmaf(f, im.w, acc[t][3]);
            }
        }
        float4* p4 = reinterpret_cast<float4*>(part);
#pragma unroll
        for (int t = 0; t < 8; t++)
            p4[(q * 8 + t) * 16 + wg] = make_float4(acc[t][0], acc[t][1], acc[t][2], acc[t][3]);
    }
    __syncthreads();

    // collapse q: tmp[t][w] (stride 68)
#pragma unroll
    for (int e = tid; e < 512; e += 256) {
        float s = 0.0f;
#pragma unroll
        for (int q2 = 0; q2 < 16; q2++) s += part[q2 * 512 + e];
        tmp[(e >> 6) * 68 + (e & 63)] = s;
    }
    __syncthreads();

    // phase C: x[t][s] = sum_w tmp[t][w] * F_w[w][s]; thread = (r 0..3, ts 0..63)
    {
        int r = tid >> 6, ts = tid & 63;
        int t2 = ts >> 3, s2 = ts & 7;
        float a2 = 0.0f;
#pragma unroll
        for (int k = 0; k < 16; k++) {
            int w = r * 16 + k;
            a2 = fmaf(tmp[t2 * 68 + w], sFwT[w * 8 + s2], a2);
        }
        xpart[r * 64 + ts] = a2;
    }
    __syncthreads();

    if (tid < 64) {
        float x = xpart[tid] + xpart[64 + tid] + xpart[128 + tid] + xpart[192 + tid];
        __nv_bfloat16 hi = __float2bfloat16(x);
        __nv_bfloat16 lo = __float2bfloat16(x - __bfloat162float(hi));
        d_x_hi[b * 64 + tid] = hi;
        d_x_lo[b * 64 + tid] = lo;
    }
}

// ---------------- fused GEMM (mma.sync bf16 split) + LSTM --------------------
// grid (64, 4), 256 threads = 8 warps (wm 0..1 x wn 0..3). CTA tile M=64 x N=128.
// warp tile 32 rows x 32 cols. 9 K-chunks of 64 (3 split terms x 3 k-blocks).
// smem: sA[2] 64x144B (2x9216), sB[2] 128x144B (2x18432) = 55296 total;
//       g_s 64x136 floats (34816) OVERLAYS sA/sB after the MMA loop.
#define SA_OFF(b) ((b) * 9216)
#define SB_OFF(b) (18432 + (b) * 18432)
#define GS_TOTAL  55296

__global__ __launch_bounds__(256) void gemm_lstm_kernel(float* __restrict__ out, int last)
{
    extern __shared__ char smem[];
    uint32_t sb = smem_u32(smem);
    int tid = threadIdx.x;
    int wid = tid >> 5, lane = tid & 31;
    int wm = wid & 1, wn = wid >> 1;          // rows wm*32..+31, cols wn*32..+31
    int bm0 = blockIdx.x * 64;
    int bn0 = blockIdx.y * 128;
    int j0 = bn0 >> 2;

    const int tva[3] = {0, 0, 1};
    const int tvb[3] = {0, 1, 0};

    float acc[2][4][4];
#pragma unroll
    for (int mt = 0; mt < 2; mt++)
#pragma unroll
        for (int nt = 0; nt < 4; nt++)
#pragma unroll
            for (int q = 0; q < 4; q++) acc[mt][nt][q] = 0.0f;

    int ldr = tid >> 3;          // 0..31
    int ldc = tid & 7;           // 16B segment

#define ISSUE_LOADS(c, buf) do {                                                   \
        int t_ = (c) / 3, kb_ = (c) % 3;                                           \
        const __nv_bfloat16* xs_ = tva[t_] ? d_x_lo : d_x_hi;                      \
        const __nv_bfloat16* hs_ = tva[t_] ? d_h_lo : d_h_hi;                      \
        const __nv_bfloat16* ws_ = tvb[t_] ? d_W_lo : d_W_hi;                      \
        _Pragma("unroll")                                                          \
        for (int p_ = 0; p_ < 2; p_++) {                                           \
            int r_ = ldr + p_ * 32;                                                \
            const __nv_bfloat16* ga_;                                              \
            if (kb_ == 0) ga_ = xs_ + (bm0 + r_) * 64 + ldc * 8;                   \
            else          ga_ = hs_ + (bm0 + r_) * 128 + (kb_ - 1) * 64 + ldc * 8; \
            cp_async16(sb + SA_OFF(buf) + r_ * 144 + ldc * 16, ga_);               \
        }                                                                          \
        _Pragma("unroll")                                                          \
        for (int p_ = 0; p_ < 4; p_++) {                                           \
            int r_ = ldr + p_ * 32;                                                \
            const __nv_bfloat16* gb_ = ws_ + (bn0 + r_) * 192 + kb_ * 64 + ldc * 8;\
            cp_async16(sb + SB_OFF(buf) + r_ * 144 + ldc * 16, gb_);               \
        }                                                                          \
        cp_commit();                                                               \
    } while (0)

    ISSUE_LOADS(0, 0);

    uint32_t a_rowofs = (uint32_t)((lane & 15) * 144 + (lane >> 4) * 16);
    uint32_t b_rowofs = (uint32_t)((lane & 7) * 144 + ((lane >> 3) & 1) * 16);

    for (int c = 0; c < 9; c++) {
        int buf = c & 1;
        if (c < 8) ISSUE_LOADS(c + 1, buf ^ 1);
        if (c < 8) cp_wait<1>(); else cp_wait<0>();
        __syncthreads();

        uint32_t abase = sb + SA_OFF(buf) + wm * 32 * 144 + a_rowofs;
        uint32_t bbase = sb + SB_OFF(buf) + wn * 32 * 144 + b_rowofs;

#pragma unroll
        for (int ks = 0; ks < 4; ks++) {
            uint32_t a[2][4], bfr[4][2];
            ldm_x4(a[0], abase + ks * 32);
            ldm_x4(a[1], abase + 16 * 144 + ks * 32);
#pragma unroll
            for (int nt = 0; nt < 4; nt++)
                ldm_x2(bfr[nt], bbase + nt * (8 * 144) + ks * 32);
#pragma unroll
            for (int mt = 0; mt < 2; mt++)
#pragma unroll
                for (int nt = 0; nt < 4; nt++)
                    mma_bf16(acc[mt][nt], a[mt], bfr[nt]);
        }
        __syncthreads();
    }
#undef ISSUE_LOADS

    // store accumulators to gates smem tile (overlays sA/sB — dead now)
    float* g_s = reinterpret_cast<float*>(smem);   // [64][136]
    {
        int r0 = wm * 32 + (lane >> 2);
        int c0 = wn * 32 + (lane & 3) * 2;
#pragma unroll
        for (int mt = 0; mt < 2; mt++)
#pragma unroll
            for (int nt = 0; nt < 4; nt++) {
                int row = r0 + mt * 16;
                int col = c0 + nt * 8;
                *reinterpret_cast<float2*>(&g_s[row * 136 + col]) =
                    make_float2(acc[mt][nt][0], acc[mt][nt][1]);
                *reinterpret_cast<float2*>(&g_s[(row + 8) * 136 + col]) =
                    make_float2(acc[mt][nt][2], acc[mt][nt][3]);
            }
    }
    __syncthreads();

    // fused LSTM pointwise, coalesced global traffic
    const float4* bias4 = reinterpret_cast<const float4*>(d_bias + bn0);
#pragma unroll
    for (int i = tid; i < 64 * 32; i += 256) {
        int row = i >> 5, j = i & 31;
        float4 g4 = *reinterpret_cast<const float4*>(&g_s[row * 136 + 4 * j]);
        float4 b4 = __ldg(&bias4[j]);
        float gi = g4.x + b4.x;
        float gf = g4.y + b4.y;
        float gg = g4.z + b4.z;
        float go = g4.w + b4.w;
        int gidx = (bm0 + row) * 128 + j0 + j;
        float co = d_c[gidx];
        float si = 1.0f / (1.0f + expf(-gi));
        float sf = 1.0f / (1.0f + expf(-gf));
        float so = 1.0f / (1.0f + expf(-go));
        float cn = sf * co + si * tanhf(gg);
        float hn = so * tanhf(cn);
        d_c[gidx] = cn;
        if (last) {
            out[gidx] = hn;
        } else {
            d_h[gidx] = hn;
            __nv_bfloat16 hi = __float2bfloat16(hn);
            d_h_hi[gidx] = hi;
            d_h_lo[gidx] = __float2bfloat16(hn - __bfloat162float(hi));
        }
    }
}

// ---------------- launch ----------------------------------------------------
extern "C" void kernel_launch(void* const* d_in, const int* in_sizes, int n_in,
                              void* d_out, int out_size)
{
    const float* imgs = (const float*)d_in[0];
    const float* W_ih = (const float*)d_in[1];
    const float* W_hh = (const float*)d_in[2];
    const float* b_ih = (const float*)d_in[3];
    const float* b_hh = (const float*)d_in[4];
    const float* W_g  = (const float*)d_in[5];
    const float* b_g  = (const float*)d_in[6];
    float* out = (float*)d_out;

    static int smem_set = 0;
    if (!smem_set) {
        cudaFuncSetAttribute(gemm_lstm_kernel,
                             cudaFuncAttributeMaxDynamicSharedMemorySize, GS_TOTAL);
        cudaFuncSetAttribute(glimpse_kernel,
                             cudaFuncAttributeMaxDynamicSharedMemorySize, GL_TOTAL);
        smem_set = 1;
    }

    zero_state_kernel<<<(BATCH * HID + 255) / 256, 256>>>();
    prep_weights_kernel<<<(512 * 192 + 255) / 256, 256>>>(W_ih, W_hh, b_ih, b_hh);

    for (int t = 0; t < NSTEP; t++) {
        glimpse_kernel<<<BATCH, 256, GL_TOTAL>>>(imgs, t & 1, W_g, b_g);
        gemm_lstm_kernel<<<dim3(64, 4), 256, GS_TOTAL>>>(out, t == NSTEP - 1 ? 1 : 0);
    }
}

// round 5
// speedup vs baseline: 1.7694x; 1.0495x over previous
#include <cuda_runtime.h>
#include <cuda_bf16.h>
#include <cuda_fp16.h>
#include <math.h>
#include <stdint.h>

#define BATCH 4096
#define HID 128
#define NSTEP 16

// ---------------- persistent state (device globals; no allocations) ----------
__device__ float d_h[BATCH * HID];
__device__ float d_c[BATCH * HID];
__device__ __align__(16) __nv_bfloat16 d_h_hi[BATCH * HID];
__device__ __align__(16) __nv_bfloat16 d_h_lo[BATCH * HID];
__device__ __align__(16) __nv_bfloat16 d_x_hi[BATCH * 64];
__device__ __align__(16) __nv_bfloat16 d_x_lo[BATCH * 64];
__device__ __align__(16) __nv_bfloat16 d_W_hi[512 * 192];   // reordered cols: n' = j*4+gate
__device__ __align__(16) __nv_bfloat16 d_W_lo[512 * 192];
__device__ __align__(16) float d_bias[512];                  // reordered
__device__ __align__(16) __half d_img_h[(size_t)BATCH * 2 * 4096];  // fp16 images (67MB)

// ---------------- helpers ----------------------------------------------------
__device__ __forceinline__ uint32_t smem_u32(const void* p) {
    uint32_t a;
    asm("{ .reg .u64 t; cvta.to.shared.u64 t, %1; cvt.u32.u64 %0, t; }" : "=r"(a) : "l"(p));
    return a;
}
__device__ __forceinline__ void cp_async16(uint32_t dst, const void* src) {
    asm volatile("cp.async.cg.shared.global [%0], [%1], 16;" :: "r"(dst), "l"(src) : "memory");
}
__device__ __forceinline__ void cp_commit() {
    asm volatile("cp.async.commit_group;" ::: "memory");
}
template <int N>
__device__ __forceinline__ void cp_wait() {
    asm volatile("cp.async.wait_group %0;" :: "n"(N) : "memory");
}
__device__ __forceinline__ void ldm_x4(uint32_t* r, uint32_t a) {
    asm volatile("ldmatrix.sync.aligned.m8n8.x4.shared.b16 {%0,%1,%2,%3}, [%4];"
                 : "=r"(r[0]), "=r"(r[1]), "=r"(r[2]), "=r"(r[3]) : "r"(a));
}
__device__ __forceinline__ void ldm_x2(uint32_t* r, uint32_t a) {
    asm volatile("ldmatrix.sync.aligned.m8n8.x2.shared.b16 {%0,%1}, [%2];"
                 : "=r"(r[0]), "=r"(r[1]) : "r"(a));
}
__device__ __forceinline__ void mma_bf16(float* d, const uint32_t* a, const uint32_t* b) {
    asm volatile(
        "mma.sync.aligned.m16n8k16.row.col.f32.bf16.bf16.f32 "
        "{%0,%1,%2,%3}, {%4,%5,%6,%7}, {%8,%9}, {%0,%1,%2,%3};"
        : "+f"(d[0]), "+f"(d[1]), "+f"(d[2]), "+f"(d[3])
        : "r"(a[0]), "r"(a[1]), "r"(a[2]), "r"(a[3]), "r"(b[0]), "r"(b[1]));
}

// ---------------- prologue kernels -------------------------------------------
__global__ void zero_state_kernel() {
    int i = blockIdx.x * blockDim.x + threadIdx.x;
    if (i < BATCH * HID) {
        d_h[i] = 0.0f; d_c[i] = 0.0f;
        d_h_hi[i] = __float2bfloat16(0.0f);
        d_h_lo[i] = __float2bfloat16(0.0f);
    }
}

// fp32 -> fp16 image conversion (once per launch; both images then L2-resident)
__global__ void img_convert_kernel(const float* __restrict__ imgs) {
    const float4* in4 = reinterpret_cast<const float4*>(imgs);
    uint2* out2 = reinterpret_cast<uint2*>(d_img_h);
    int stride = gridDim.x * blockDim.x;
    for (int i = blockIdx.x * blockDim.x + threadIdx.x; i < 8388608; i += stride) {
        float4 v = in4[i];
        __half2 a = __floats2half2_rn(v.x, v.y);
        __half2 c = __floats2half2_rn(v.z, v.w);
        uint2 o;
        o.x = *reinterpret_cast<uint32_t*>(&a);
        o.y = *reinterpret_cast<uint32_t*>(&c);
        out2[i] = o;
    }
}

// reorder columns: n' = j*4 + gate (gate: 0=i,1=f,2=g,3=o), split fp32->bf16 hi/lo
__global__ void prep_weights_kernel(const float* __restrict__ W_ih,
                                    const float* __restrict__ W_hh,
                                    const float* __restrict__ b_ih,
                                    const float* __restrict__ b_hh) {
    int idx = blockIdx.x * blockDim.x + threadIdx.x;   // 512*192
    if (idx >= 512 * 192) return;
    int np = idx / 192, k = idx % 192;
    int gate = np & 3, j = np >> 2;
    int orig = gate * 128 + j;
    float w = (k < 64) ? W_ih[orig * 64 + k] : W_hh[orig * 128 + (k - 64)];
    __nv_bfloat16 hi = __float2bfloat16(w);
    __nv_bfloat16 lo = __float2bfloat16(w - __bfloat162float(hi));
    d_W_hi[np * 192 + k] = hi;
    d_W_lo[np * 192 + k] = lo;
    if (k == 0) d_bias[np] = b_ih[orig] + b_hh[orig];
}

// ---------------- glimpse ----------------------------------------------------
// dynamic smem layout (bytes):
//   simg_h @0      8192   [64][64] fp16
//   sF     @8192   4096   [2][8][64]   sF[a][t][i] = F_a[i][t]
//   sFwT   @12288  2048   [64][8]      F_w[w][s]
//   part   @14336 32768   [16][8][64]
//   tmp    @47104  2176   [8][68]
//   xpart  @49280  1024   [4][64]
//   sred   @50304    96   [3][8]
//   sgp    @50400    12
#define GL_TOTAL 50432

__global__ __launch_bounds__(256) void glimpse_kernel(
    int sel, const float* __restrict__ W_g, const float* __restrict__ b_g)
{
    extern __shared__ char gsm[];
    __half* simg_h = reinterpret_cast<__half*>(gsm);
    float* sF    = reinterpret_cast<float*>(gsm + 8192);
    float* sFwT  = reinterpret_cast<float*>(gsm + 12288);
    float* part  = reinterpret_cast<float*>(gsm + 14336);
    float* tmp   = reinterpret_cast<float*>(gsm + 47104);
    float* xpart = reinterpret_cast<float*>(gsm + 49280);
    float* sred  = reinterpret_cast<float*>(gsm + 50304);
    float* sgp   = reinterpret_cast<float*>(gsm + 50400);

    int b = blockIdx.x;
    int tid = threadIdx.x;
    uint32_t sbg = smem_u32(gsm);

    // async image load (fp16, 8KB); consumed only in phase B
    {
        const __half* imgp = d_img_h + ((size_t)b * 2 + (size_t)sel) * 4096;
        cp_async16(sbg + tid * 16, imgp + tid * 8);
        cp_async16(sbg + 4096 + tid * 16, imgp + 2048 + tid * 8);
        cp_commit();
    }

    // gp = tanh(h @ W_g^T + b_g)
    float v = 0.0f;
    if (tid < HID) v = d_h[b * HID + tid];
#pragma unroll
    for (int k = 0; k < 3; k++) {
        float p = (tid < HID) ? v * W_g[k * HID + tid] : 0.0f;
#pragma unroll
        for (int o = 16; o > 0; o >>= 1) p += __shfl_down_sync(0xffffffffu, p, o);
        if ((tid & 31) == 0) sred[k * 8 + (tid >> 5)] = p;
    }
    __syncthreads();
    if (tid < 3) {
        float s = 0.0f;
#pragma unroll
        for (int w = 0; w < 8; w++) s += sred[tid * 8 + w];
        sgp[tid] = tanhf(s + b_g[tid]);
    }
    __syncthreads();

    float ad  = fabsf(sgp[2]);
    float dlt = 8.0f * (1.0f - ad);
    float gam = expf(1.0f - 2.0f * ad);
    float inv_gam = 1.0f / gam;
    float cpre = 1.0f / (3.14159265358979323f * gam);

    // unnormalized Cauchy filters
#pragma unroll
    for (int j = 0; j < 4; j++) {
        int idx = tid + j * 256;
        int a = idx >> 9, t = (idx >> 6) & 7, i = idx & 63;
        float center = 31.5f * (sgp[a] + 1.0f);
        float gpix = center + dlt * ((float)t - 3.5f);
        float u = ((float)i - gpix) * inv_gam;
        sF[(a * 8 + t) * 64 + i] = cpre / (1.0f + u * u);
    }
    __syncthreads();

    // normalize 16 (a,t) columns over i
    {
        int warp = tid >> 5, lane = tid & 31;
#pragma unroll
        for (int j = 0; j < 2; j++) {
            int col = warp * 2 + j;
            float* fc = sF + col * 64;
            float s = fc[lane] + fc[lane + 32];
#pragma unroll
            for (int o = 16; o > 0; o >>= 1) s += __shfl_down_sync(0xffffffffu, s, o);
            s = __shfl_sync(0xffffffffu, s, 0);
            float inv = 1.0f / (s + 1e-4f);
            fc[lane]      *= inv;
            fc[lane + 32] *= inv;
        }
    }
    __syncthreads();

    // transposed F_w copy: sFwT[w][s] = sF[1][s][w]
#pragma unroll
    for (int j = 0; j < 2; j++) {
        int idx = tid + j * 256;
        int w = idx >> 3, s = idx & 7;
        sFwT[w * 8 + s] = sF[(8 + s) * 64 + w];
    }
    cp_wait<0>();
    __syncthreads();

    // phase B: part[q][t][w] — thread = (wg 0..15 [4 w], q 0..15 [4 i])
    {
        int wg = tid & 15, q = tid >> 4;
        float acc[8][4];
#pragma unroll
        for (int t = 0; t < 8; t++)
#pragma unroll
            for (int u = 0; u < 4; u++) acc[t][u] = 0.0f;
        const uint2* sg2 = reinterpret_cast<const uint2*>(simg_h);
#pragma unroll
        for (int ii = 0; ii < 4; ii++) {
            int i = q * 4 + ii;
            uint2 raw = sg2[i * 16 + wg];
            float2 f01 = __half22float2(*reinterpret_cast<__half2*>(&raw.x));
            float2 f23 = __half22float2(*reinterpret_cast<__half2*>(&raw.y));
#pragma unroll
            for (int t = 0; t < 8; t++) {
                float f = sF[t * 64 + i];
                acc[t][0] = fmaf(f, f01.x, acc[t][0]);
                acc[t][1] = fmaf(f, f01.y, acc[t][1]);
                acc[t][2] = fmaf(f, f23.x, acc[t][2]);
                acc[t][3] = fmaf(f, f23.y, acc[t][3]);
            }
        }
        float4* p4 = reinterpret_cast<float4*>(part);
#pragma unroll
        for (int t = 0; t < 8; t++)
            p4[(q * 8 + t) * 16 + wg] = make_float4(acc[t][0], acc[t][1], acc[t][2], acc[t][3]);
    }
    __syncthreads();

    // collapse q: tmp[t][w] (stride 68)
#pragma unroll
    for (int e = tid; e < 512; e += 256) {
        float s = 0.0f;
#pragma unroll
        for (int q2 = 0; q2 < 16; q2++) s += part[q2 * 512 + e];
        tmp[(e >> 6) * 68 + (e & 63)] = s;
    }
    __syncthreads();

    // phase C: x[t][s] = sum_w tmp[t][w] * F_w[w][s]; thread = (r 0..3, ts 0..63)
    {
        int r = tid >> 6, ts = tid & 63;
        int t2 = ts >> 3, s2 = ts & 7;
        float a2 = 0.0f;
#pragma unroll
        for (int k = 0; k < 16; k++) {
            int w = r * 16 + k;
            a2 = fmaf(tmp[t2 * 68 + w], sFwT[w * 8 + s2], a2);
        }
        xpart[r * 64 + ts] = a2;
    }
    __syncthreads();

    if (tid < 64) {
        float x = xpart[tid] + xpart[64 + tid] + xpart[128 + tid] + xpart[192 + tid];
        __nv_bfloat16 hi = __float2bfloat16(x);
        __nv_bfloat16 lo = __float2bfloat16(x - __bfloat162float(hi));
        d_x_hi[b * 64 + tid] = hi;
        d_x_lo[b * 64 + tid] = lo;
    }
}

// ---------------- fused GEMM (mma.sync bf16 split) + LSTM --------------------
// grid (128, 4), 256 threads = 8 warps (wm 0..1 x wn 0..3). CTA tile M=32 x N=128.
// warp tile 16 rows x 32 cols. 9 K-chunks of 64 (3 split terms x 3 k-blocks).
// smem: sA[2] 32x144B (2x4608), sB[2] 128x144B (2x18432) = 46080 total;
//       g_s 32x136 floats (17408) OVERLAYS sA/sB after the MMA loop.
#define SA_OFF(b) ((b) * 4608)
#define SB_OFF(b) (9216 + (b) * 18432)
#define GS_TOTAL  46080

__global__ __launch_bounds__(256) void gemm_lstm_kernel(float* __restrict__ out, int last)
{
    extern __shared__ char smem[];
    uint32_t sb = smem_u32(smem);
    int tid = threadIdx.x;
    int wid = tid >> 5, lane = tid & 31;
    int wm = wid & 1, wn = wid >> 1;          // rows wm*16..+15, cols wn*32..+31
    int bm0 = blockIdx.x * 32;
    int bn0 = blockIdx.y * 128;
    int j0 = bn0 >> 2;

    const int tva[3] = {0, 0, 1};
    const int tvb[3] = {0, 1, 0};

    float acc[4][4];
#pragma unroll
    for (int nt = 0; nt < 4; nt++)
#pragma unroll
        for (int q = 0; q < 4; q++) acc[nt][q] = 0.0f;

    int ldr = tid >> 3;          // 0..31
    int ldc = tid & 7;           // 16B segment

#define ISSUE_LOADS(c, buf) do {                                                   \
        int t_ = (c) / 3, kb_ = (c) % 3;                                           \
        const __nv_bfloat16* xs_ = tva[t_] ? d_x_lo : d_x_hi;                      \
        const __nv_bfloat16* hs_ = tva[t_] ? d_h_lo : d_h_hi;                      \
        const __nv_bfloat16* ws_ = tvb[t_] ? d_W_lo : d_W_hi;                      \
        {                                                                          \
            const __nv_bfloat16* ga_;                                              \
            if (kb_ == 0) ga_ = xs_ + (bm0 + ldr) * 64 + ldc * 8;                  \
            else          ga_ = hs_ + (bm0 + ldr) * 128 + (kb_ - 1) * 64 + ldc * 8;\
            cp_async16(sb + SA_OFF(buf) + ldr * 144 + ldc * 16, ga_);              \
        }                                                                          \
        _Pragma("unroll")                                                          \
        for (int p_ = 0; p_ < 4; p_++) {                                           \
            int r_ = ldr + p_ * 32;                                                \
            const __nv_bfloat16* gb_ = ws_ + (bn0 + r_) * 192 + kb_ * 64 + ldc * 8;\
            cp_async16(sb + SB_OFF(buf) + r_ * 144 + ldc * 16, gb_);               \
        }                                                                          \
        cp_commit();                                                               \
    } while (0)

    ISSUE_LOADS(0, 0);

    uint32_t a_rowofs = (uint32_t)((lane & 15) * 144 + (lane >> 4) * 16);
    uint32_t b_rowofs = (uint32_t)((lane & 7) * 144 + ((lane >> 3) & 1) * 16);

    for (int c = 0; c < 9; c++) {
        int buf = c & 1;
        if (c < 8) ISSUE_LOADS(c + 1, buf ^ 1);
        if (c < 8) cp_wait<1>(); else cp_wait<0>();
        __syncthreads();

        uint32_t abase = sb + SA_OFF(buf) + wm * 16 * 144 + a_rowofs;
        uint32_t bbase = sb + SB_OFF(buf) + wn * 32 * 144 + b_rowofs;

#pragma unroll
        for (int ks = 0; ks < 4; ks++) {
            uint32_t a[4], bfr[4][2];
            ldm_x4(a, abase + ks * 32);
#pragma unroll
            for (int nt = 0; nt < 4; nt++)
                ldm_x2(bfr[nt], bbase + nt * (8 * 144) + ks * 32);
#pragma unroll
            for (int nt = 0; nt < 4; nt++)
                mma_bf16(acc[nt], a, bfr[nt]);
        }
        __syncthreads();
    }
#undef ISSUE_LOADS

    // store accumulators to gates smem tile (overlays sA/sB — dead now)
    float* g_s = reinterpret_cast<float*>(smem);   // [32][136]
    {
        int r0 = wm * 16 + (lane >> 2);
        int c0 = wn * 32 + (lane & 3) * 2;
#pragma unroll
        for (int nt = 0; nt < 4; nt++) {
            int col = c0 + nt * 8;
            *reinterpret_cast<float2*>(&g_s[r0 * 136 + col]) =
                make_float2(acc[nt][0], acc[nt][1]);
            *reinterpret_cast<float2*>(&g_s[(r0 + 8) * 136 + col]) =
                make_float2(acc[nt][2], acc[nt][3]);
        }
    }
    __syncthreads();

    // fused LSTM pointwise, coalesced global traffic
    const float4* bias4 = reinterpret_cast<const float4*>(d_bias + bn0);
#pragma unroll
    for (int i = tid; i < 32 * 32; i += 256) {
        int row = i >> 5, j = i & 31;
        float4 g4 = *reinterpret_cast<const float4*>(&g_s[row * 136 + 4 * j]);
        float4 b4 = __ldg(&bias4[j]);
        float gi = g4.x + b4.x;
        float gf = g4.y + b4.y;
        float gg = g4.z + b4.z;
        float go = g4.w + b4.w;
        int gidx = (bm0 + row) * 128 + j0 + j;
        float co = d_c[gidx];
        float si = 1.0f / (1.0f + expf(-gi));
        float sf = 1.0f / (1.0f + expf(-gf));
        float so = 1.0f / (1.0f + expf(-go));
        float cn = sf * co + si * tanhf(gg);
        float hn = so * tanhf(cn);
        d_c[gidx] = cn;
        if (last) {
            out[gidx] = hn;
        } else {
            d_h[gidx] = hn;
            __nv_bfloat16 hi = __float2bfloat16(hn);
            d_h_hi[gidx] = hi;
            d_h_lo[gidx] = __float2bfloat16(hn - __bfloat162float(hi));
        }
    }
}

// ---------------- launch ----------------------------------------------------
extern "C" void kernel_launch(void* const* d_in, const int* in_sizes, int n_in,
                              void* d_out, int out_size)
{
    const float* imgs = (const float*)d_in[0];
    const float* W_ih = (const float*)d_in[1];
    const float* W_hh = (const float*)d_in[2];
    const float* b_ih = (const float*)d_in[3];
    const float* b_hh = (const float*)d_in[4];
    const float* W_g  = (const float*)d_in[5];
    const float* b_g  = (const float*)d_in[6];
    float* out = (float*)d_out;

    static int smem_set = 0;
    if (!smem_set) {
        cudaFuncSetAttribute(gemm_lstm_kernel,
                             cudaFuncAttributeMaxDynamicSharedMemorySize, GS_TOTAL);
        cudaFuncSetAttribute(glimpse_kernel,
                             cudaFuncAttributeMaxDynamicSharedMemorySize, GL_TOTAL);
        smem_set = 1;
    }

    zero_state_kernel<<<(BATCH * HID + 255) / 256, 256>>>();
    img_convert_kernel<<<8192, 256>>>(imgs);
    prep_weights_kernel<<<(512 * 192 + 255) / 256, 256>>>(W_ih, W_hh, b_ih, b_hh);

    for (int t = 0; t < NSTEP; t++) {
        glimpse_kernel<<<BATCH, 256, GL_TOTAL>>>(t & 1, W_g, b_g);
        gemm_lstm_kernel<<<dim3(128, 4), 256, GS_TOTAL>>>(out, t == NSTEP - 1 ? 1 : 0);
    }
}

// round 6
// speedup vs baseline: 2.6119x; 1.4762x over previous
#include <cuda_runtime.h>
#include <cuda_bf16.h>
#include <cuda_fp16.h>
#include <math.h>
#include <stdint.h>

#define BATCH 4096
#define HID 128
#define NSTEP 16

// ---------------- persistent state (device globals; no allocations) ----------
__device__ __align__(16) float d_h[BATCH * HID];
__device__ __align__(16) float d_c[BATCH * HID];
__device__ __align__(16) __nv_bfloat16 d_h_hi[BATCH * HID];
__device__ __align__(16) __nv_bfloat16 d_h_lo[BATCH * HID];
__device__ __align__(16) __nv_bfloat16 d_x_hi[BATCH * 64];
__device__ __align__(16) __nv_bfloat16 d_x_lo[BATCH * 64];
__device__ __align__(16) __nv_bfloat16 d_W_hi[512 * 192];   // reordered cols: n' = j*4+gate
__device__ __align__(16) __nv_bfloat16 d_W_lo[512 * 192];
__device__ __align__(16) float d_bias[512];                  // reordered
__device__ __align__(16) __half d_img_h[(size_t)BATCH * 2 * 4096];  // fp16 images (67MB)

// ---------------- helpers ----------------------------------------------------
__device__ __forceinline__ uint32_t smem_u32(const void* p) {
    uint32_t a;
    asm("{ .reg .u64 t; cvta.to.shared.u64 t, %1; cvt.u32.u64 %0, t; }" : "=r"(a) : "l"(p));
    return a;
}
__device__ __forceinline__ void cp_async16(uint32_t dst, const void* src) {
    asm volatile("cp.async.cg.shared.global [%0], [%1], 16;" :: "r"(dst), "l"(src) : "memory");
}
__device__ __forceinline__ void cp_commit() {
    asm volatile("cp.async.commit_group;" ::: "memory");
}
template <int N>
__device__ __forceinline__ void cp_wait() {
    asm volatile("cp.async.wait_group %0;" :: "n"(N) : "memory");
}
__device__ __forceinline__ void ldm_x4(uint32_t* r, uint32_t a) {
    asm volatile("ldmatrix.sync.aligned.m8n8.x4.shared.b16 {%0,%1,%2,%3}, [%4];"
                 : "=r"(r[0]), "=r"(r[1]), "=r"(r[2]), "=r"(r[3]) : "r"(a));
}
__device__ __forceinline__ void ldm_x4_t(uint32_t* r, uint32_t a) {
    asm volatile("ldmatrix.sync.aligned.m8n8.x4.trans.shared.b16 {%0,%1,%2,%3}, [%4];"
                 : "=r"(r[0]), "=r"(r[1]), "=r"(r[2]), "=r"(r[3]) : "r"(a));
}
__device__ __forceinline__ void ldm_x2(uint32_t* r, uint32_t a) {
    asm volatile("ldmatrix.sync.aligned.m8n8.x2.shared.b16 {%0,%1}, [%2];"
                 : "=r"(r[0]), "=r"(r[1]) : "r"(a));
}
__device__ __forceinline__ void mma_bf16(float* d, const uint32_t* a, const uint32_t* b) {
    asm volatile(
        "mma.sync.aligned.m16n8k16.row.col.f32.bf16.bf16.f32 "
        "{%0,%1,%2,%3}, {%4,%5,%6,%7}, {%8,%9}, {%0,%1,%2,%3};"
        : "+f"(d[0]), "+f"(d[1]), "+f"(d[2]), "+f"(d[3])
        : "r"(a[0]), "r"(a[1]), "r"(a[2]), "r"(a[3]), "r"(b[0]), "r"(b[1]));
}
__device__ __forceinline__ void mma_f16(float* d, const uint32_t* a, const uint32_t* b) {
    asm volatile(
        "mma.sync.aligned.m16n8k16.row.col.f32.f16.f16.f32 "
        "{%0,%1,%2,%3}, {%4,%5,%6,%7}, {%8,%9}, {%0,%1,%2,%3};"
        : "+f"(d[0]), "+f"(d[1]), "+f"(d[2]), "+f"(d[3])
        : "r"(a[0]), "r"(a[1]), "r"(a[2]), "r"(a[3]), "r"(b[0]), "r"(b[1]));
}
__device__ __forceinline__ uint32_t pack_h2(float x, float y) {
    __half2 h = __floats2half2_rn(x, y);
    return *reinterpret_cast<uint32_t*>(&h);
}

// ---------------- prologue kernels -------------------------------------------
__global__ void zero_state_kernel() {
    int i = blockIdx.x * blockDim.x + threadIdx.x;
    if (i < BATCH * HID) {
        d_h[i] = 0.0f; d_c[i] = 0.0f;
        d_h_hi[i] = __float2bfloat16(0.0f);
        d_h_lo[i] = __float2bfloat16(0.0f);
    }
}

// fp32 -> fp16 image conversion (once per launch)
__global__ void img_convert_kernel(const float* __restrict__ imgs) {
    const float4* in4 = reinterpret_cast<const float4*>(imgs);
    uint2* out2 = reinterpret_cast<uint2*>(d_img_h);
    int stride = gridDim.x * blockDim.x;
    for (int i = blockIdx.x * blockDim.x + threadIdx.x; i < 8388608; i += stride) {
        float4 v = in4[i];
        __half2 a = __floats2half2_rn(v.x, v.y);
        __half2 c = __floats2half2_rn(v.z, v.w);
        uint2 o;
        o.x = *reinterpret_cast<uint32_t*>(&a);
        o.y = *reinterpret_cast<uint32_t*>(&c);
        out2[i] = o;
    }
}

// reorder columns: n' = j*4 + gate (gate: 0=i,1=f,2=g,3=o), split fp32->bf16 hi/lo
__global__ void prep_weights_kernel(const float* __restrict__ W_ih,
                                    const float* __restrict__ W_hh,
                                    const float* __restrict__ b_ih,
                                    const float* __restrict__ b_hh) {
    int idx = blockIdx.x * blockDim.x + threadIdx.x;   // 512*192
    if (idx >= 512 * 192) return;
    int np = idx / 192, k = idx % 192;
    int gate = np & 3, j = np >> 2;
    int orig = gate * 128 + j;
    float w = (k < 64) ? W_ih[orig * 64 + k] : W_hh[orig * 128 + (k - 64)];
    __nv_bfloat16 hi = __float2bfloat16(w);
    __nv_bfloat16 lo = __float2bfloat16(w - __bfloat162float(hi));
    d_W_hi[np * 192 + k] = hi;
    d_W_lo[np * 192 + k] = lo;
    if (k == 0) d_bias[np] = b_ih[orig] + b_hh[orig];
}

// ---------------- glimpse (tensor-core version) ------------------------------
// 128 threads = 4 warps, each warp handles one sample end-to-end.
// smem per block:
//   img[s]   @ s*9216           64 rows x 144B (fp16, 64 valid halfs/row)
//   FhA[s,t] @ 36864+s*4608+t*2304   16 rows x 144B fp16 (rows 8..15 zero)
//   FwB[s,t] @ 55296+s*2304+t*1152    8 rows x 144B fp16
#define GL2_IMG(s)    ((s) * 9216)
#define GL2_FH(s)     (36864 + (s) * 4608)
#define GL2_FW(s)     (55296 + (s) * 2304)
#define GL2_TOTAL     64512

__global__ __launch_bounds__(128) void glimpse_kernel(
    int sel, const float* __restrict__ W_g, const float* __restrict__ b_g)
{
    extern __shared__ char gsm[];
    uint32_t sb = smem_u32(gsm);
    int tid = threadIdx.x, wid = tid >> 5, lane = tid & 31;
    int b0 = blockIdx.x * 4;
    int b = b0 + wid;

    // issue image cp.async: 4 samples x 64 rows x 8 chunks of 16B
#pragma unroll
    for (int j = 0; j < 16; j++) {
        int idx = tid + j * 128;
        int s = idx >> 9, r = (idx >> 3) & 63, c = idx & 7;
        const __half* src = d_img_h + ((size_t)(b0 + s) * 2 + (size_t)sel) * 4096 + r * 64 + c * 8;
        cp_async16(sb + GL2_IMG(s) + r * 144 + c * 16, src);
    }
    cp_commit();

    // zero the whole FhA region (rows 8..15 must be zero): 18432 B = 1152 uint4
#pragma unroll
    for (int j = 0; j < 9; j++) {
        int idx = tid + j * 128;
        *reinterpret_cast<uint4*>(gsm + 36864 + idx * 16) = make_uint4(0, 0, 0, 0);
    }

    // ---- gp = tanh(h @ W_g^T + b_g) (per warp) ----
    float4 hv = *reinterpret_cast<const float4*>(&d_h[b * 128 + lane * 4]);
    float gp[3];
#pragma unroll
    for (int k = 0; k < 3; k++) {
        float4 wv = __ldg(reinterpret_cast<const float4*>(&W_g[k * 128 + lane * 4]));
        float p = hv.x * wv.x + hv.y * wv.y + hv.z * wv.z + hv.w * wv.w;
#pragma unroll
        for (int o = 16; o > 0; o >>= 1) p += __shfl_xor_sync(0xffffffffu, p, o);
        gp[k] = tanhf(p + __ldg(&b_g[k]));
    }
    __syncthreads();   // FhA zero fill complete before filter stores

    // ---- Cauchy filterbanks, normalized, fp16 hi/lo, straight into smem ----
    {
        float ad  = fabsf(gp[2]);
        float dlt = 8.0f * (1.0f - ad);
        float gam = expf(1.0f - 2.0f * ad);
        float ig  = 1.0f / gam;
        float cpre = 1.0f / (3.14159265358979323f * gam);
        float fi0 = (float)(2 * lane), fi1 = fi0 + 1.0f;
#pragma unroll
        for (int a = 0; a < 2; a++) {
            float center = 31.5f * (gp[a] + 1.0f);
            uint32_t base = (a == 0) ? (uint32_t)GL2_FH(wid) : (uint32_t)GL2_FW(wid);
            uint32_t term = (a == 0) ? 2304u : 1152u;
#pragma unroll
            for (int t = 0; t < 8; t++) {
                float gpix = center + dlt * ((float)t - 3.5f);
                float u0 = (fi0 - gpix) * ig, u1 = (fi1 - gpix) * ig;
                float v0 = __fdividef(cpre, 1.0f + u0 * u0);
                float v1 = __fdividef(cpre, 1.0f + u1 * u1);
                float s = v0 + v1;
#pragma unroll
                for (int o = 16; o > 0; o >>= 1) s += __shfl_xor_sync(0xffffffffu, s, o);
                float inv = __fdividef(1.0f, s + 1e-4f);
                v0 *= inv; v1 *= inv;
                uint32_t hi2 = pack_h2(v0, v1);
                __half2 hh = *reinterpret_cast<__half2*>(&hi2);
                float2 hf = __half22float2(hh);
                uint32_t lo2 = pack_h2(v0 - hf.x, v1 - hf.y);
                char* dst = gsm + base + t * 144 + lane * 4;
                *reinterpret_cast<uint32_t*>(dst) = hi2;
                *reinterpret_cast<uint32_t*>(dst + term) = lo2;
            }
        }
    }
    cp_wait<0>();
    __syncthreads();

    // ---- G1: P[16,64] = FhA(16x64, hi+lo) @ img(64x64) ----
    float acc[8][4];
#pragma unroll
    for (int nt = 0; nt < 8; nt++)
#pragma unroll
        for (int q = 0; q < 4; q++) acc[nt][q] = 0.0f;

    uint32_t fh_hi = sb + GL2_FH(wid) + (lane & 15) * 144 + (lane >> 4) * 16;
    uint32_t fh_lo = fh_hi + 2304;
    uint32_t imgb  = sb + GL2_IMG(wid) + (lane & 15) * 144 + (lane >> 4) * 16;

#pragma unroll
    for (int kk = 0; kk < 4; kk++) {
        uint32_t ah[4], al[4];
        ldm_x4(ah, fh_hi + kk * 32);
        ldm_x4(al, fh_lo + kk * 32);
#pragma unroll
        for (int nt2 = 0; nt2 < 4; nt2++) {
            uint32_t bb[4];
            ldm_x4_t(bb, imgb + kk * (16 * 144) + nt2 * 32);
            mma_f16(acc[2 * nt2],     ah, bb);
            mma_f16(acc[2 * nt2 + 1], ah, bb + 2);
            mma_f16(acc[2 * nt2],     al, bb);
            mma_f16(acc[2 * nt2 + 1], al, bb + 2);
        }
    }

    // ---- G2: x[8,8] = P(hi+lo) @ FwB(64x8, hi+lo minus lo*lo) ----
    float acc2[4] = {0.0f, 0.0f, 0.0f, 0.0f};
    uint32_t fwb = sb + GL2_FW(wid) + (lane & 7) * 144 + ((lane >> 3) & 1) * 16;
#pragma unroll
    for (int kk2 = 0; kk2 < 4; kk2++) {
        uint32_t ah[4], al[4];
#pragma unroll
        for (int half2i = 0; half2i < 2; half2i++) {
            float x0 = acc[2 * kk2 + half2i][0], x1 = acc[2 * kk2 + half2i][1];
            float y0 = acc[2 * kk2 + half2i][2], y1 = acc[2 * kk2 + half2i][3];
            uint32_t h0 = pack_h2(x0, x1);
            uint32_t h1 = pack_h2(y0, y1);
            __half2 hh0 = *reinterpret_cast<__half2*>(&h0);
            __half2 hh1 = *reinterpret_cast<__half2*>(&h1);
            float2 f0 = __half22float2(hh0);
            float2 f1 = __half22float2(hh1);
            ah[2 * half2i]     = h0;
            ah[2 * half2i + 1] = h1;
            al[2 * half2i]     = pack_h2(x0 - f0.x, x1 - f0.y);
            al[2 * half2i + 1] = pack_h2(y0 - f1.x, y1 - f1.y);
        }
        uint32_t bh[2], bl[2];
        ldm_x2(bh, fwb + kk2 * 32);
        ldm_x2(bl, fwb + 1152 + kk2 * 32);
        mma_f16(acc2, ah, bh);
        mma_f16(acc2, al, bh);
        mma_f16(acc2, ah, bl);
    }

    // ---- writeback x (rows 0..7 of the 16-row tile are valid) ----
    {
        int t = lane >> 2, c2 = (lane & 3) * 2;
        float v0 = acc2[0], v1 = acc2[1];
        __nv_bfloat16 h0 = __float2bfloat16(v0);
        __nv_bfloat16 h1 = __float2bfloat16(v1);
        __nv_bfloat162 hi2 = __nv_bfloat162(h0, h1);
        __nv_bfloat162 lo2 = __nv_bfloat162(
            __float2bfloat16(v0 - __bfloat162float(h0)),
            __float2bfloat16(v1 - __bfloat162float(h1)));
        *reinterpret_cast<__nv_bfloat162*>(&d_x_hi[b * 64 + t * 8 + c2]) = hi2;
        *reinterpret_cast<__nv_bfloat162*>(&d_x_lo[b * 64 + t * 8 + c2]) = lo2;
    }
}

// ---------------- fused GEMM (mma.sync bf16 split) + LSTM --------------------
// grid (128, 4), 256 threads = 8 warps (wm 0..1 x wn 0..3). CTA tile M=32 x N=128.
#define SA_OFF(b) ((b) * 4608)
#define SB_OFF(b) (9216 + (b) * 18432)
#define GS_TOTAL  46080

__global__ __launch_bounds__(256) void gemm_lstm_kernel(float* __restrict__ out, int last)
{
    extern __shared__ char smem[];
    uint32_t sb = smem_u32(smem);
    int tid = threadIdx.x;
    int wid = tid >> 5, lane = tid & 31;
    int wm = wid & 1, wn = wid >> 1;          // rows wm*16..+15, cols wn*32..+31
    int bm0 = blockIdx.x * 32;
    int bn0 = blockIdx.y * 128;
    int j0 = bn0 >> 2;

    const int tva[3] = {0, 0, 1};
    const int tvb[3] = {0, 1, 0};

    float acc[4][4];
#pragma unroll
    for (int nt = 0; nt < 4; nt++)
#pragma unroll
        for (int q = 0; q < 4; q++) acc[nt][q] = 0.0f;

    int ldr = tid >> 3;          // 0..31
    int ldc = tid & 7;           // 16B segment

#define ISSUE_LOADS(c, buf) do {                                                   \
        int t_ = (c) / 3, kb_ = (c) % 3;                                           \
        const __nv_bfloat16* xs_ = tva[t_] ? d_x_lo : d_x_hi;                      \
        const __nv_bfloat16* hs_ = tva[t_] ? d_h_lo : d_h_hi;                      \
        const __nv_bfloat16* ws_ = tvb[t_] ? d_W_lo : d_W_hi;                      \
        {                                                                          \
            const __nv_bfloat16* ga_;                                              \
            if (kb_ == 0) ga_ = xs_ + (bm0 + ldr) * 64 + ldc * 8;                  \
            else          ga_ = hs_ + (bm0 + ldr) * 128 + (kb_ - 1) * 64 + ldc * 8;\
            cp_async16(sb + SA_OFF(buf) + ldr * 144 + ldc * 16, ga_);              \
        }                                                                          \
        _Pragma("unroll")                                                          \
        for (int p_ = 0; p_ < 4; p_++) {                                           \
            int r_ = ldr + p_ * 32;                                                \
            const __nv_bfloat16* gb_ = ws_ + (bn0 + r_) * 192 + kb_ * 64 + ldc * 8;\
            cp_async16(sb + SB_OFF(buf) + r_ * 144 + ldc * 16, gb_);               \
        }                                                                          \
        cp_commit();                                                               \
    } while (0)

    ISSUE_LOADS(0, 0);

    uint32_t a_rowofs = (uint32_t)((lane & 15) * 144 + (lane >> 4) * 16);
    uint32_t b_rowofs = (uint32_t)((lane & 7) * 144 + ((lane >> 3) & 1) * 16);

    for (int c = 0; c < 9; c++) {
        int buf = c & 1;
        if (c < 8) ISSUE_LOADS(c + 1, buf ^ 1);
        if (c < 8) cp_wait<1>(); else cp_wait<0>();
        __syncthreads();

        uint32_t abase = sb + SA_OFF(buf) + wm * 16 * 144 + a_rowofs;
        uint32_t bbase = sb + SB_OFF(buf) + wn * 32 * 144 + b_rowofs;

#pragma unroll
        for (int ks = 0; ks < 4; ks++) {
            uint32_t a[4], bfr[4][2];
            ldm_x4(a, abase + ks * 32);
#pragma unroll
            for (int nt = 0; nt < 4; nt++)
                ldm_x2(bfr[nt], bbase + nt * (8 * 144) + ks * 32);
#pragma unroll
            for (int nt = 0; nt < 4; nt++)
                mma_bf16(acc[nt], a, bfr[nt]);
        }
        __syncthreads();
    }
#undef ISSUE_LOADS

    // store accumulators to gates smem tile (overlays sA/sB — dead now)
    float* g_s = reinterpret_cast<float*>(smem);   // [32][136]
    {
        int r0 = wm * 16 + (lane >> 2);
        int c0 = wn * 32 + (lane & 3) * 2;
#pragma unroll
        for (int nt = 0; nt < 4; nt++) {
            int col = c0 + nt * 8;
            *reinterpret_cast<float2*>(&g_s[r0 * 136 + col]) =
                make_float2(acc[nt][0], acc[nt][1]);
            *reinterpret_cast<float2*>(&g_s[(r0 + 8) * 136 + col]) =
                make_float2(acc[nt][2], acc[nt][3]);
        }
    }
    __syncthreads();

    // fused LSTM pointwise, coalesced global traffic
    const float4* bias4 = reinterpret_cast<const float4*>(d_bias + bn0);
#pragma unroll
    for (int i = tid; i < 32 * 32; i += 256) {
        int row = i >> 5, j = i & 31;
        float4 g4 = *reinterpret_cast<const float4*>(&g_s[row * 136 + 4 * j]);
        float4 b4 = __ldg(&bias4[j]);
        float gi = g4.x + b4.x;
        float gf = g4.y + b4.y;
        float gg = g4.z + b4.z;
        float go = g4.w + b4.w;
        int gidx = (bm0 + row) * 128 + j0 + j;
        float co = d_c[gidx];
        float si = 1.0f / (1.0f + expf(-gi));
        float sf = 1.0f / (1.0f + expf(-gf));
        float so = 1.0f / (1.0f + expf(-go));
        float cn = sf * co + si * tanhf(gg);
        float hn = so * tanhf(cn);
        d_c[gidx] = cn;
        if (last) {
            out[gidx] = hn;
        } else {
            d_h[gidx] = hn;
            __nv_bfloat16 hi = __float2bfloat16(hn);
            d_h_hi[gidx] = hi;
            d_h_lo[gidx] = __float2bfloat16(hn - __bfloat162float(hi));
        }
    }
}

// ---------------- launch ----------------------------------------------------
extern "C" void kernel_launch(void* const* d_in, const int* in_sizes, int n_in,
                              void* d_out, int out_size)
{
    const float* imgs = (const float*)d_in[0];
    const float* W_ih = (const float*)d_in[1];
    const float* W_hh = (const float*)d_in[2];
    const float* b_ih = (const float*)d_in[3];
    const float* b_hh = (const float*)d_in[4];
    const float* W_g  = (const float*)d_in[5];
    const float* b_g  = (const float*)d_in[6];
    float* out = (float*)d_out;

    static int smem_set = 0;
    if (!smem_set) {
        cudaFuncSetAttribute(gemm_lstm_kernel,
                             cudaFuncAttributeMaxDynamicSharedMemorySize, GS_TOTAL);
        cudaFuncSetAttribute(glimpse_kernel,
                             cudaFuncAttributeMaxDynamicSharedMemorySize, GL2_TOTAL);
        smem_set = 1;
    }

    zero_state_kernel<<<(BATCH * HID + 255) / 256, 256>>>();
    img_convert_kernel<<<8192, 256>>>(imgs);
    prep_weights_kernel<<<(512 * 192 + 255) / 256, 256>>>(W_ih, W_hh, b_ih, b_hh);

    for (int t = 0; t < NSTEP; t++) {
        glimpse_kernel<<<BATCH / 4, 128, GL2_TOTAL>>>(t & 1, W_g, b_g);
        gemm_lstm_kernel<<<dim3(128, 4), 256, GS_TOTAL>>>(out, t == NSTEP - 1 ? 1 : 0);
    }
}

// round 7
// speedup vs baseline: 2.9544x; 1.1311x over previous
#include <cuda_runtime.h>
#include <cuda_bf16.h>
#include <cuda_fp16.h>
#include <math.h>
#include <stdint.h>

#define BATCH 4096
#define HID 128
#define NSTEP 16

// ---------------- persistent state (device globals; no allocations) ----------
__device__ __align__(16) float d_h[BATCH * HID];
__device__ __align__(16) float d_c[BATCH * HID];
__device__ __align__(16) __nv_bfloat16 d_h_hi[BATCH * HID];
__device__ __align__(16) __nv_bfloat16 d_h_lo[BATCH * HID];
__device__ __align__(16) __nv_bfloat16 d_x_hi[BATCH * 64];
__device__ __align__(16) __nv_bfloat16 d_x_lo[BATCH * 64];
__device__ __align__(16) __nv_bfloat16 d_W_hi[512 * 192];   // reordered cols: n' = j*4+gate
__device__ __align__(16) __nv_bfloat16 d_W_lo[512 * 192];
__device__ __align__(16) float d_bias[512];                  // reordered
__device__ __align__(16) __half d_img_h[(size_t)BATCH * 2 * 4096];  // fp16 images (67MB)

// ---------------- helpers ----------------------------------------------------
__device__ __forceinline__ uint32_t smem_u32(const void* p) {
    uint32_t a;
    asm("{ .reg .u64 t; cvta.to.shared.u64 t, %1; cvt.u32.u64 %0, t; }" : "=r"(a) : "l"(p));
    return a;
}
__device__ __forceinline__ void cp_async16(uint32_t dst, const void* src) {
    asm volatile("cp.async.cg.shared.global [%0], [%1], 16;" :: "r"(dst), "l"(src) : "memory");
}
__device__ __forceinline__ void cp_commit() {
    asm volatile("cp.async.commit_group;" ::: "memory");
}
template <int N>
__device__ __forceinline__ void cp_wait() {
    asm volatile("cp.async.wait_group %0;" :: "n"(N) : "memory");
}
__device__ __forceinline__ void pdl_trigger() {
    asm volatile("griddepcontrol.launch_dependents;");
}
__device__ __forceinline__ void pdl_wait() {
    asm volatile("griddepcontrol.wait;" ::: "memory");
}
__device__ __forceinline__ void ldm_x4(uint32_t* r, uint32_t a) {
    asm volatile("ldmatrix.sync.aligned.m8n8.x4.shared.b16 {%0,%1,%2,%3}, [%4];"
                 : "=r"(r[0]), "=r"(r[1]), "=r"(r[2]), "=r"(r[3]) : "r"(a));
}
__device__ __forceinline__ void ldm_x4_t(uint32_t* r, uint32_t a) {
    asm volatile("ldmatrix.sync.aligned.m8n8.x4.trans.shared.b16 {%0,%1,%2,%3}, [%4];"
                 : "=r"(r[0]), "=r"(r[1]), "=r"(r[2]), "=r"(r[3]) : "r"(a));
}
__device__ __forceinline__ void ldm_x2(uint32_t* r, uint32_t a) {
    asm volatile("ldmatrix.sync.aligned.m8n8.x2.shared.b16 {%0,%1}, [%2];"
                 : "=r"(r[0]), "=r"(r[1]) : "r"(a));
}
__device__ __forceinline__ void mma_bf16(float* d, const uint32_t* a, const uint32_t* b) {
    asm volatile(
        "mma.sync.aligned.m16n8k16.row.col.f32.bf16.bf16.f32 "
        "{%0,%1,%2,%3}, {%4,%5,%6,%7}, {%8,%9}, {%0,%1,%2,%3};"
        : "+f"(d[0]), "+f"(d[1]), "+f"(d[2]), "+f"(d[3])
        : "r"(a[0]), "r"(a[1]), "r"(a[2]), "r"(a[3]), "r"(b[0]), "r"(b[1]));
}
__device__ __forceinline__ void mma_f16(float* d, const uint32_t* a, const uint32_t* b) {
    asm volatile(
        "mma.sync.aligned.m16n8k16.row.col.f32.f16.f16.f32 "
        "{%0,%1,%2,%3}, {%4,%5,%6,%7}, {%8,%9}, {%0,%1,%2,%3};"
        : "+f"(d[0]), "+f"(d[1]), "+f"(d[2]), "+f"(d[3])
        : "r"(a[0]), "r"(a[1]), "r"(a[2]), "r"(a[3]), "r"(b[0]), "r"(b[1]));
}
__device__ __forceinline__ uint32_t pack_h2(float x, float y) {
    __half2 h = __floats2half2_rn(x, y);
    return *reinterpret_cast<uint32_t*>(&h);
}

// ---------------- prologue kernels -------------------------------------------
__global__ void zero_state_kernel() {
    int i = blockIdx.x * blockDim.x + threadIdx.x;
    if (i < BATCH * HID) {
        d_h[i] = 0.0f; d_c[i] = 0.0f;
        d_h_hi[i] = __float2bfloat16(0.0f);
        d_h_lo[i] = __float2bfloat16(0.0f);
    }
}

// fp32 -> fp16 image conversion (once per launch)
__global__ void img_convert_kernel(const float* __restrict__ imgs) {
    const float4* in4 = reinterpret_cast<const float4*>(imgs);
    uint2* out2 = reinterpret_cast<uint2*>(d_img_h);
    int stride = gridDim.x * blockDim.x;
    for (int i = blockIdx.x * blockDim.x + threadIdx.x; i < 8388608; i += stride) {
        float4 v = in4[i];
        __half2 a = __floats2half2_rn(v.x, v.y);
        __half2 c = __floats2half2_rn(v.z, v.w);
        uint2 o;
        o.x = *reinterpret_cast<uint32_t*>(&a);
        o.y = *reinterpret_cast<uint32_t*>(&c);
        out2[i] = o;
    }
}

// reorder columns: n' = j*4 + gate (gate: 0=i,1=f,2=g,3=o), split fp32->bf16 hi/lo
__global__ void prep_weights_kernel(const float* __restrict__ W_ih,
                                    const float* __restrict__ W_hh,
                                    const float* __restrict__ b_ih,
                                    const float* __restrict__ b_hh) {
    int idx = blockIdx.x * blockDim.x + threadIdx.x;   // 512*192
    if (idx >= 512 * 192) return;
    int np = idx / 192, k = idx % 192;
    int gate = np & 3, j = np >> 2;
    int orig = gate * 128 + j;
    float w = (k < 64) ? W_ih[orig * 64 + k] : W_hh[orig * 128 + (k - 64)];
    __nv_bfloat16 hi = __float2bfloat16(w);
    __nv_bfloat16 lo = __float2bfloat16(w - __bfloat162float(hi));
    d_W_hi[np * 192 + k] = hi;
    d_W_lo[np * 192 + k] = lo;
    if (k == 0) d_bias[np] = b_ih[orig] + b_hh[orig];
}

// ---------------- glimpse (tensor-core, packed hi/lo) ------------------------
// 128 threads = 4 warps, one sample per warp.
// smem: img[s] @ s*9216 (64 rows x 144B fp16)
//       FhA[s] @ 36864 + s*2304 (16 rows x 144B: rows 0-7 = hi, 8-15 = lo)
//       FwB[s] @ 46080 + s*2304 (hi 8 rows @0, lo 8 rows @1152)
#define GL2_IMG(s)    ((s) * 9216)
#define GL2_FH(s)     (36864 + (s) * 2304)
#define GL2_FW(s)     (46080 + (s) * 2304)
#define GL2_TOTAL     55296

__global__ __launch_bounds__(128) void glimpse_kernel(
    int sel, const float* __restrict__ W_g, const float* __restrict__ b_g)
{
    extern __shared__ char gsm[];
    uint32_t sb = smem_u32(gsm);
    int tid = threadIdx.x, wid = tid >> 5, lane = tid & 31;
    int b0 = blockIdx.x * 4;
    int b = b0 + wid;

    // ---- static prefetch (images) BEFORE grid-dependency wait ----
#pragma unroll
    for (int j = 0; j < 16; j++) {
        int idx = tid + j * 128;
        int s = idx >> 9, r = (idx >> 3) & 63, c = idx & 7;
        const __half* src = d_img_h + ((size_t)(b0 + s) * 2 + (size_t)sel) * 4096 + r * 64 + c * 8;
        cp_async16(sb + GL2_IMG(s) + r * 144 + c * 16, src);
    }
    cp_commit();

    pdl_trigger();
    pdl_wait();       // d_h from gemm_{t-1} now visible

    // ---- gp = tanh(h @ W_g^T + b_g) (per warp) ----
    float4 hv = *reinterpret_cast<const float4*>(&d_h[b * 128 + lane * 4]);
    float gp[3];
#pragma unroll
    for (int k = 0; k < 3; k++) {
        float4 wv = __ldg(reinterpret_cast<const float4*>(&W_g[k * 128 + lane * 4]));
        float p = hv.x * wv.x + hv.y * wv.y + hv.z * wv.z + hv.w * wv.w;
#pragma unroll
        for (int o = 16; o > 0; o >>= 1) p += __shfl_xor_sync(0xffffffffu, p, o);
        gp[k] = tanhf(p + __ldg(&b_g[k]));
    }

    // ---- Cauchy filterbanks, normalized, fp16 hi/lo, straight into smem ----
    {
        float ad  = fabsf(gp[2]);
        float dlt = 8.0f * (1.0f - ad);
        float gam = expf(1.0f - 2.0f * ad);
        float ig  = 1.0f / gam;
        float cpre = 1.0f / (3.14159265358979323f * gam);
        float fi0 = (float)(2 * lane), fi1 = fi0 + 1.0f;
#pragma unroll
        for (int a = 0; a < 2; a++) {
            float center = 31.5f * (gp[a] + 1.0f);
            uint32_t base = (a == 0) ? (uint32_t)GL2_FH(wid) : (uint32_t)GL2_FW(wid);
#pragma unroll
            for (int t = 0; t < 8; t++) {
                float gpix = center + dlt * ((float)t - 3.5f);
                float u0 = (fi0 - gpix) * ig, u1 = (fi1 - gpix) * ig;
                float v0 = __fdividef(cpre, 1.0f + u0 * u0);
                float v1 = __fdividef(cpre, 1.0f + u1 * u1);
                float s = v0 + v1;
#pragma unroll
                for (int o = 16; o > 0; o >>= 1) s += __shfl_xor_sync(0xffffffffu, s, o);
                float inv = __fdividef(1.0f, s + 1e-4f);
                v0 *= inv; v1 *= inv;
                uint32_t hi2 = pack_h2(v0, v1);
                __half2 hh = *reinterpret_cast<__half2*>(&hi2);
                float2 hf = __half22float2(hh);
                uint32_t lo2 = pack_h2(v0 - hf.x, v1 - hf.y);
                char* dst = gsm + base + t * 144 + lane * 4;
                *reinterpret_cast<uint32_t*>(dst) = hi2;          // hi: row t
                *reinterpret_cast<uint32_t*>(dst + 1152) = lo2;   // lo: row t+8
            }
        }
    }
    cp_wait<0>();
    __syncwarp();

    // ---- G1: single pass; A rows 0-7 = Fh_hi, rows 8-15 = Fh_lo ----
    // acc rows 0-7 = hi*img, rows 8-15 = lo*img; summed per-thread afterward.
    float acc[8][4];
#pragma unroll
    for (int nt = 0; nt < 8; nt++)
#pragma unroll
        for (int q = 0; q < 4; q++) acc[nt][q] = 0.0f;

    uint32_t fh   = sb + GL2_FH(wid) + (lane & 15) * 144 + (lane >> 4) * 16;
    uint32_t imgb = sb + GL2_IMG(wid) + (lane & 15) * 144 + (lane >> 4) * 16;

#pragma unroll
    for (int kk = 0; kk < 4; kk++) {
        uint32_t ah[4];
        ldm_x4(ah, fh + kk * 32);
#pragma unroll
        for (int nt2 = 0; nt2 < 4; nt2++) {
            uint32_t bb[4];
            ldm_x4_t(bb, imgb + kk * (16 * 144) + nt2 * 32);
            mma_f16(acc[2 * nt2],     ah, bb);
            mma_f16(acc[2 * nt2 + 1], ah, bb + 2);
        }
    }

    // sum hi/lo halves: P_true[t] = acc(row t) + acc(row t+8)
    float ps[8][2];
#pragma unroll
    for (int nt = 0; nt < 8; nt++) {
        ps[nt][0] = acc[nt][0] + acc[nt][2];
        ps[nt][1] = acc[nt][1] + acc[nt][3];
    }

    // ---- G2: x[8,8] = P(hi+lo) @ FwB(hi+lo, minus lo*lo) ----
    float acc2[4] = {0.0f, 0.0f, 0.0f, 0.0f};
    uint32_t fwb = sb + GL2_FW(wid) + (lane & 7) * 144 + ((lane >> 3) & 1) * 16;
#pragma unroll
    for (int kk2 = 0; kk2 < 4; kk2++) {
        float p0 = ps[2 * kk2][0],     p1 = ps[2 * kk2][1];
        float q0 = ps[2 * kk2 + 1][0], q1 = ps[2 * kk2 + 1][1];
        uint32_t ah[4], al[4];
        ah[0] = pack_h2(p0, p1);
        ah[2] = pack_h2(q0, q1);
        ah[1] = 0u; ah[3] = 0u;
        {
            __half2 h0 = *reinterpret_cast<__half2*>(&ah[0]);
            __half2 h2 = *reinterpret_cast<__half2*>(&ah[2]);
            float2 f0 = __half22float2(h0);
            float2 f2 = __half22float2(h2);
            al[0] = pack_h2(p0 - f0.x, p1 - f0.y);
            al[2] = pack_h2(q0 - f2.x, q1 - f2.y);
            al[1] = 0u; al[3] = 0u;
        }
        uint32_t bh[2], bl[2];
        ldm_x2(bh, fwb + kk2 * 32);
        ldm_x2(bl, fwb + 1152 + kk2 * 32);
        mma_f16(acc2, ah, bh);
        mma_f16(acc2, al, bh);
        mma_f16(acc2, ah, bl);
    }

    // ---- writeback x (rows 0..7 valid) ----
    {
        int t = lane >> 2, c2 = (lane & 3) * 2;
        float v0 = acc2[0], v1 = acc2[1];
        __nv_bfloat16 h0 = __float2bfloat16(v0);
        __nv_bfloat16 h1 = __float2bfloat16(v1);
        __nv_bfloat162 hi2 = __nv_bfloat162(h0, h1);
        __nv_bfloat162 lo2 = __nv_bfloat162(
            __float2bfloat16(v0 - __bfloat162float(h0)),
            __float2bfloat16(v1 - __bfloat162float(h1)));
        *reinterpret_cast<__nv_bfloat162*>(&d_x_hi[b * 64 + t * 8 + c2]) = hi2;
        *reinterpret_cast<__nv_bfloat162*>(&d_x_lo[b * 64 + t * 8 + c2]) = lo2;
    }
}

// ---------------- fused GEMM (mma.sync bf16 split) + LSTM --------------------
// grid (128, 4), 256 threads = 8 warps (wm 0..1 x wn 0..3). CTA tile M=32 x N=128.
#define SA_OFF(b) ((b) * 4608)
#define SB_OFF(b) (9216 + (b) * 18432)
#define GS_TOTAL  46080

__global__ __launch_bounds__(256) void gemm_lstm_kernel(float* __restrict__ out, int last)
{
    extern __shared__ char smem[];
    uint32_t sb = smem_u32(smem);
    int tid = threadIdx.x;
    int wid = tid >> 5, lane = tid & 31;
    int wm = wid & 1, wn = wid >> 1;          // rows wm*16..+15, cols wn*32..+31
    int bm0 = blockIdx.x * 32;
    int bn0 = blockIdx.y * 128;
    int j0 = bn0 >> 2;

    const int tva[3] = {0, 0, 1};
    const int tvb[3] = {0, 1, 0};

    float acc[4][4];
#pragma unroll
    for (int nt = 0; nt < 4; nt++)
#pragma unroll
        for (int q = 0; q < 4; q++) acc[nt][q] = 0.0f;

    int ldr = tid >> 3;          // 0..31
    int ldc = tid & 7;           // 16B segment

    // ---- static prefetch: chunk0 B tile (W_hi, k block 0) before grid wait ----
#pragma unroll
    for (int p_ = 0; p_ < 4; p_++) {
        int r_ = ldr + p_ * 32;
        cp_async16(sb + SB_OFF(0) + r_ * 144 + ldc * 16,
                   d_W_hi + (bn0 + r_) * 192 + ldc * 8);
    }
    cp_commit();                 // group g0

    pdl_trigger();
    pdl_wait();                  // glimpse_t (and transitively gemm_{t-1}) complete

    // chunk0 A tile (x_hi) — dependent data
    cp_async16(sb + SA_OFF(0) + ldr * 144 + ldc * 16,
               d_x_hi + (bm0 + ldr) * 64 + ldc * 8);
    cp_commit();                 // group g1

#define ISSUE_LOADS(c, buf) do {                                                   \
        int t_ = (c) / 3, kb_ = (c) % 3;                                           \
        const __nv_bfloat16* xs_ = tva[t_] ? d_x_lo : d_x_hi;                      \
        const __nv_bfloat16* hs_ = tva[t_] ? d_h_lo : d_h_hi;                      \
        const __nv_bfloat16* ws_ = tvb[t_] ? d_W_lo : d_W_hi;                      \
        {                                                                          \
            const __nv_bfloat16* ga_;                                              \
            if (kb_ == 0) ga_ = xs_ + (bm0 + ldr) * 64 + ldc * 8;                  \
            else          ga_ = hs_ + (bm0 + ldr) * 128 + (kb_ - 1) * 64 + ldc * 8;\
            cp_async16(sb + SA_OFF(buf) + ldr * 144 + ldc * 16, ga_);              \
        }                                                                          \
        _Pragma("unroll")                                                          \
        for (int p_ = 0; p_ < 4; p_++) {                                           \
            int r_ = ldr + p_ * 32;                                                \
            const __nv_bfloat16* gb_ = ws_ + (bn0 + r_) * 192 + kb_ * 64 + ldc * 8;\
            cp_async16(sb + SB_OFF(buf) + r_ * 144 + ldc * 16, gb_);               \
        }                                                                          \
        cp_commit();                                                               \
    } while (0)

    uint32_t a_rowofs = (uint32_t)((lane & 15) * 144 + (lane >> 4) * 16);
    uint32_t b_rowofs = (uint32_t)((lane & 7) * 144 + ((lane >> 3) & 1) * 16);

    for (int c = 0; c < 9; c++) {
        int buf = c & 1;
        if (c < 8) ISSUE_LOADS(c + 1, buf ^ 1);
        if (c < 8) cp_wait<1>(); else cp_wait<0>();
        __syncthreads();

        uint32_t abase = sb + SA_OFF(buf) + wm * 16 * 144 + a_rowofs;
        uint32_t bbase = sb + SB_OFF(buf) + wn * 32 * 144 + b_rowofs;

#pragma unroll
        for (int ks = 0; ks < 4; ks++) {
            uint32_t a[4], bfr[4][2];
            ldm_x4(a, abase + ks * 32);
#pragma unroll
            for (int nt = 0; nt < 4; nt++)
                ldm_x2(bfr[nt], bbase + nt * (8 * 144) + ks * 32);
#pragma unroll
            for (int nt = 0; nt < 4; nt++)
                mma_bf16(acc[nt], a, bfr[nt]);
        }
        __syncthreads();
    }
#undef ISSUE_LOADS

    // store accumulators to gates smem tile (overlays sA/sB — dead now)
    float* g_s = reinterpret_cast<float*>(smem);   // [32][136]
    {
        int r0 = wm * 16 + (lane >> 2);
        int c0 = wn * 32 + (lane & 3) * 2;
#pragma unroll
        for (int nt = 0; nt < 4; nt++) {
            int col = c0 + nt * 8;
            *reinterpret_cast<float2*>(&g_s[r0 * 136 + col]) =
                make_float2(acc[nt][0], acc[nt][1]);
            *reinterpret_cast<float2*>(&g_s[(r0 + 8) * 136 + col]) =
                make_float2(acc[nt][2], acc[nt][3]);
        }
    }
    __syncthreads();

    // fused LSTM pointwise, coalesced global traffic
    const float4* bias4 = reinterpret_cast<const float4*>(d_bias + bn0);
#pragma unroll
    for (int i = tid; i < 32 * 32; i += 256) {
        int row = i >> 5, j = i & 31;
        float4 g4 = *reinterpret_cast<const float4*>(&g_s[row * 136 + 4 * j]);
        float4 b4 = __ldg(&bias4[j]);
        float gi = g4.x + b4.x;
        float gf = g4.y + b4.y;
        float gg = g4.z + b4.z;
        float go = g4.w + b4.w;
        int gidx = (bm0 + row) * 128 + j0 + j;
        float co = d_c[gidx];
        float si = 1.0f / (1.0f + expf(-gi));
        float sf = 1.0f / (1.0f + expf(-gf));
        float so = 1.0f / (1.0f + expf(-go));
        float cn = sf * co + si * tanhf(gg);
        float hn = so * tanhf(cn);
        d_c[gidx] = cn;
        if (last) {
            out[gidx] = hn;
        } else {
            d_h[gidx] = hn;
            __nv_bfloat16 hi = __float2bfloat16(hn);
            d_h_hi[gidx] = hi;
            d_h_lo[gidx] = __float2bfloat16(hn - __bfloat162float(hi));
        }
    }
}

// ---------------- launch ----------------------------------------------------
extern "C" void kernel_launch(void* const* d_in, const int* in_sizes, int n_in,
                              void* d_out, int out_size)
{
    const float* imgs = (const float*)d_in[0];
    const float* W_ih = (const float*)d_in[1];
    const float* W_hh = (const float*)d_in[2];
    const float* b_ih = (const float*)d_in[3];
    const float* b_hh = (const float*)d_in[4];
    const float* W_g  = (const float*)d_in[5];
    const float* b_g  = (const float*)d_in[6];
    float* out = (float*)d_out;

    static int smem_set = 0;
    if (!smem_set) {
        cudaFuncSetAttribute(gemm_lstm_kernel,
                             cudaFuncAttributeMaxDynamicSharedMemorySize, GS_TOTAL);
        cudaFuncSetAttribute(glimpse_kernel,
                             cudaFuncAttributeMaxDynamicSharedMemorySize, GL2_TOTAL);
        smem_set = 1;
    }

    zero_state_kernel<<<(BATCH * HID + 255) / 256, 256>>>();
    img_convert_kernel<<<8192, 256>>>(imgs);
    prep_weights_kernel<<<(512 * 192 + 255) / 256, 256>>>(W_ih, W_hh, b_ih, b_hh);

    cudaLaunchAttribute pdl_attr[1];
    pdl_attr[0].id = cudaLaunchAttributeProgrammaticStreamSerialization;
    pdl_attr[0].val.programmaticStreamSerializationAllowed = 1;

    for (int t = 0; t < NSTEP; t++) {
        {
            cudaLaunchConfig_t cfg = {};
            cfg.gridDim = dim3(BATCH / 4, 1, 1);
            cfg.blockDim = dim3(128, 1, 1);
            cfg.dynamicSmemBytes = GL2_TOTAL;
            cfg.stream = 0;
            cfg.attrs = pdl_attr;
            cfg.numAttrs = 1;
            cudaLaunchKernelEx(&cfg, glimpse_kernel, t & 1, W_g, b_g);
        }
        {
            cudaLaunchConfig_t cfg = {};
            cfg.gridDim = dim3(128, 4, 1);
            cfg.blockDim = dim3(256, 1, 1);
            cfg.dynamicSmemBytes = GS_TOTAL;
            cfg.stream = 0;
            cfg.attrs = pdl_attr;
            cfg.numAttrs = 1;
            cudaLaunchKernelEx(&cfg, gemm_lstm_kernel, out,
                               (t == NSTEP - 1) ? 1 : 0);
        }
    }
}